// round 11
// baseline (speedup 1.0000x reference)
#include <cuda_runtime.h>
#include <cuda_bf16.h>
#include <cstdint>

// ---------------- static problem config ----------------
#define BG   64
#define NPG  512
#define NN   (BG*NPG)     // 32768
#define EPG  8192
#define EE   (BG*EPG)     // 524288
#define LTOK 16
#define HD   256
#define PD   128
#define KP1  256
#define KP2  128
#define N2   (BG*KP1)     // 16384

// ---------------- device scratch ----------------
__device__ float g_w[EE];
__device__ float g_h[NN*HD];
__device__ float g_y[NN*HD];
__device__ __nv_bfloat16 g_xhi[NN*HD];
__device__ __nv_bfloat16 g_xlo[NN*HD];
__device__ float g_deg[NN];
__device__ float g_score[NN];
__device__ float g_ydw[NN];
__device__ float g_gatev[NN];
__device__ int   g_cnt[NN];
__device__ int   g_rowstart[NN];
__device__ int   g_csr[EE];
__device__ float g_csrw[EE];
__device__ int   g_nof[NN];
__device__ int   g_oldidx[NN];
__device__ float g_out[BG*HD];
__device__ float g_pn[2*HD];
__device__ __nv_bfloat16 g_WThi[2][HD*HD];
__device__ __nv_bfloat16 g_WTlo[2][HD*HD];

// ---------------- helpers ----------------
__device__ __forceinline__ uint32_t smem_u32(const void* p) {
    uint32_t a;
    asm("{ .reg .u64 t; cvta.to.shared.u64 t, %1; cvt.u32.u64 %0, t; }" : "=r"(a) : "l"(p));
    return a;
}
__device__ __forceinline__ void cp_async16(uint32_t dst, const void* src) {
    asm volatile("cp.async.ca.shared.global [%0], [%1], 16;" :: "r"(dst), "l"(src) : "memory");
}
#define CP_COMMIT() asm volatile("cp.async.commit_group;" ::: "memory")
#define CP_WAIT(n)  asm volatile("cp.async.wait_group %0;" :: "n"(n) : "memory")

__device__ __forceinline__ void split4(float4 v, uint2& hi, uint2& lo) {
    __nv_bfloat162 h0 = __floats2bfloat162_rn(v.x, v.y);
    __nv_bfloat162 h1 = __floats2bfloat162_rn(v.z, v.w);
    float rx = v.x - __bfloat162float(__low2bfloat16(h0));
    float ry = v.y - __bfloat162float(__high2bfloat16(h0));
    float rz = v.z - __bfloat162float(__low2bfloat16(h1));
    float rw = v.w - __bfloat162float(__high2bfloat16(h1));
    __nv_bfloat162 l0 = __floats2bfloat162_rn(rx, ry);
    __nv_bfloat162 l1 = __floats2bfloat162_rn(rz, rw);
    hi = make_uint2(*(uint32_t*)&h0, *(uint32_t*)&h1);
    lo = make_uint2(*(uint32_t*)&l0, *(uint32_t*)&l1);
}

// ---------------- ST encoder (node-range; fused nof=-1) -------------------
__global__ void __launch_bounds__(256) st_encode_kernel(const int* __restrict__ tokens,
                                                        const float* __restrict__ emb,
                                                        int node0) {
    int tid = threadIdx.x;
    int grp = tid >> 6, lane = tid & 63;
    int nbase = node0 + blockIdx.x * 4;
    int node = nbase + grp;
    __shared__ int toks[4*LTOK];
    if (tid < 4*LTOK) toks[tid] = tokens[nbase*LTOK + tid];
    if (lane == 0) g_nof[node] = -1;
    __syncthreads();
    const float4* emb4 = (const float4*)emb;
    float4 acc = {0.f, 0.f, 0.f, 0.f};
    int cnt = 0;
    #pragma unroll
    for (int l = 0; l < LTOK; l++) {
        int t = toks[grp*LTOK + l];
        if (t != 0) {
            float4 v = emb4[(size_t)t*64 + lane];
            acc.x += v.x; acc.y += v.y; acc.z += v.z; acc.w += v.w;
            cnt++;
        }
    }
    float inv = 1.f / (float)(cnt > 0 ? cnt : 1);
    acc.x *= inv; acc.y *= inv; acc.z *= inv; acc.w *= inv;
    size_t o = (size_t)node*64 + lane;
    uint2 hi, lo;
    split4(acc, hi, lo);
    ((uint2*)g_xhi)[o] = hi;
    ((uint2*)g_xlo)[o] = lo;
}

// ---------------- W^T bf16 split ----------------
__global__ void wsplit_kernel(const float* __restrict__ W0, const float* __restrict__ W1) {
    int b = blockIdx.x;
    int which = b >> 8, k = b & 255, n = threadIdx.x;
    const float* W = which ? W1 : W0;
    float v = W[k*HD + n];
    __nv_bfloat16 hi = __float2bfloat16(v);
    float lo = v - __bfloat162float(hi);
    g_WThi[which][n*HD + k] = hi;
    g_WTlo[which][n*HD + k] = __float2bfloat16(lo);
}

// ---------------- normalized p0,p1 ----------------
__global__ void normp_kernel(const float* __restrict__ p0, const float* __restrict__ p1) {
    __shared__ float red[HD];
    int which = blockIdx.x, tid = threadIdx.x;
    const float* p = which ? p1 : p0;
    float v = p[tid];
    red[tid] = v*v; __syncthreads();
    for (int s = HD/2; s > 0; s >>= 1) {
        if (tid < s) red[tid] += red[tid+s];
        __syncthreads();
    }
    g_pn[which*HD + tid] = v / sqrtf(red[0]);
}

// ======== fused edge pipeline, layer 1 (graph range) =========
__global__ void __launch_bounds__(1024) edge_build1_kernel(const float* __restrict__ ea,
                                                           const int* __restrict__ src,
                                                           const int* __restrict__ dst,
                                                           int g0) {
    __shared__ float sdeg[NPG];
    __shared__ int   scnt[NPG];
    __shared__ float sdinv[NPG];
    __shared__ int   scur[NPG];
    __shared__ int   sscan[NPG];
    int g = g0 + blockIdx.x, tid = threadIdx.x;
    int ebase = g * EPG;
    if (tid < NPG) { sdeg[tid] = 1.0f; scnt[tid] = 0; }
    __syncthreads();
    #pragma unroll
    for (int k = 0; k < EPG/1024; k++) {
        int e = ebase + k*1024 + tid;
        float w = 0.5f * (ea[2*e] + ea[2*e+1]);
        g_w[e] = w;
        int dl = dst[e] - g*NPG;
        atomicAdd(&sdeg[dl], w);
        atomicAdd(&scnt[dl], 1);
    }
    __syncthreads();
    int c = 0;
    if (tid < NPG) {
        int node = g*NPG + tid;
        float dg = sdeg[tid];
        c = scnt[tid];
        sdinv[tid] = rsqrtf(dg);
        g_deg[node] = dg;
        g_cnt[node] = c;
        sscan[tid] = c;
    }
    __syncthreads();
    for (int off = 1; off < NPG; off <<= 1) {
        int v = (tid >= off && tid < NPG) ? sscan[tid-off] : 0;
        __syncthreads();
        if (tid < NPG) sscan[tid] += v;
        __syncthreads();
    }
    if (tid < NPG) {
        int rs = ebase + sscan[tid] - c;
        g_rowstart[g*NPG + tid] = rs;
        scur[tid] = rs;
    }
    __syncthreads();
    #pragma unroll
    for (int k = 0; k < EPG/1024; k++) {
        int e = ebase + k*1024 + tid;
        int sl = src[e] - g*NPG;
        int dl = dst[e] - g*NPG;
        float w = g_w[e];
        int pos = atomicAdd(&scur[dl], 1);
        g_csr[pos]  = g*NPG + sl;
        g_csrw[pos] = sdinv[sl] * w * sdinv[dl];
    }
}

// ======== fused edge pipeline, layer 2 (graph range) ======
__global__ void __launch_bounds__(1024) edge_build2_kernel(const int* __restrict__ src,
                                                           const int* __restrict__ dst,
                                                           int g0) {
    __shared__ float sdeg[KP1];
    __shared__ int   scnt[KP1];
    __shared__ float sdinv[KP1];
    __shared__ int   scur[KP1];
    __shared__ int   sscan[KP1];
    int g = g0 + blockIdx.x, tid = threadIdx.x;
    int ebase = g * EPG;
    if (tid < KP1) { sdeg[tid] = 1.0f; scnt[tid] = 0; }
    __syncthreads();
    #pragma unroll
    for (int k = 0; k < EPG/1024; k++) {
        int e = ebase + k*1024 + tid;
        int ns = g_nof[src[e]], nd = g_nof[dst[e]];
        if (ns >= 0 && nd >= 0) {
            float w = g_w[e];
            int dl = nd - g*KP1;
            atomicAdd(&sdeg[dl], w);
            atomicAdd(&scnt[dl], 1);
        }
    }
    __syncthreads();
    int c = 0;
    if (tid < KP1) {
        int node = g*KP1 + tid;
        float dg = sdeg[tid];
        c = scnt[tid];
        sdinv[tid] = rsqrtf(dg);
        g_deg[node] = dg;
        g_cnt[node] = c;
        sscan[tid] = c;
    }
    __syncthreads();
    for (int off = 1; off < KP1; off <<= 1) {
        int v = (tid >= off && tid < KP1) ? sscan[tid-off] : 0;
        __syncthreads();
        if (tid < KP1) sscan[tid] += v;
        __syncthreads();
    }
    if (tid < KP1) {
        int rs = ebase + sscan[tid] - c;
        g_rowstart[g*KP1 + tid] = rs;
        scur[tid] = rs;
    }
    __syncthreads();
    #pragma unroll
    for (int k = 0; k < EPG/1024; k++) {
        int e = ebase + k*1024 + tid;
        int ns = g_nof[src[e]], nd = g_nof[dst[e]];
        if (ns >= 0 && nd >= 0) {
            float w = g_w[e];
            int sl = ns - g*KP1, dl = nd - g*KP1;
            int pos = atomicAdd(&scur[dl], 1);
            g_csr[pos]  = ns;
            g_csrw[pos] = sdinv[sl] * w * sdinv[dl];
        }
    }
}

// ================= mma.sync bf16-split GEMM, cp.async double-buffered ====
#define ASTR 72
#define OFF_AH 0
#define OFF_AL (128*ASTR)
#define OFF_BH (2*128*ASTR)
#define OFF_BL (3*128*ASTR)
#define BUF_ELEMS (4*128*ASTR)
#define GEMM_SMEM (2*BUF_ELEMS*2)

__device__ __forceinline__ void mma_bf16(float* c, const uint32_t* a,
                                         uint32_t b0, uint32_t b1) {
    asm volatile(
        "mma.sync.aligned.m16n8k16.row.col.f32.bf16.bf16.f32 "
        "{%0,%1,%2,%3},{%4,%5,%6,%7},{%8,%9},{%0,%1,%2,%3};"
        : "+f"(c[0]), "+f"(c[1]), "+f"(c[2]), "+f"(c[3])
        : "r"(a[0]), "r"(a[1]), "r"(a[2]), "r"(a[3]), "r"(b0), "r"(b1));
}

__global__ void __launch_bounds__(256, 1) gemm_mma_kernel(int which, int bm0,
                                                          float* __restrict__ C) {
    extern __shared__ __align__(16) __nv_bfloat16 sm[];
    int tid = threadIdx.x;
    int bm = bm0 + blockIdx.x, bn = blockIdx.y;
    int warp = tid >> 5, lane = tid & 31;
    int wm = warp >> 1, wn = warp & 1;
    int gg = lane >> 2, tt = lane & 3;

    const __nv_bfloat16* Ah = g_xhi + (size_t)(bm*128) * HD;
    const __nv_bfloat16* Al = g_xlo + (size_t)(bm*128) * HD;
    const __nv_bfloat16* Bh = g_WThi[which] + (size_t)(bn*128) * HD;
    const __nv_bfloat16* Bl = g_WTlo[which] + (size_t)(bn*128) * HD;

    uint32_t sbase = smem_u32(sm);

    float acc[2][8][4];
    #pragma unroll
    for (int mt = 0; mt < 2; mt++)
        #pragma unroll
        for (int nt = 0; nt < 8; nt++)
            #pragma unroll
            for (int q = 0; q < 4; q++) acc[mt][nt][q] = 0.f;

    auto issue = [&](int kc, int buf) {
        uint32_t bb = sbase + buf * (BUF_ELEMS*2);
        #pragma unroll
        for (int it = 0; it < 4; it++) {
            int u = it*256 + tid;
            int row = u >> 3, seg = u & 7;
            size_t go = (size_t)row*HD + kc*64 + seg*8;
            uint32_t so = (row*ASTR + seg*8) * 2;
            cp_async16(bb + OFF_AH*2 + so, Ah + go);
            cp_async16(bb + OFF_AL*2 + so, Al + go);
            cp_async16(bb + OFF_BH*2 + so, Bh + go);
            cp_async16(bb + OFF_BL*2 + so, Bl + go);
        }
        CP_COMMIT();
    };

    issue(0, 0);
    #pragma unroll
    for (int kc = 0; kc < 4; kc++) {
        if (kc < 3) { issue(kc+1, (kc+1)&1); CP_WAIT(1); }
        else        { CP_WAIT(0); }
        __syncthreads();
        const __nv_bfloat16* buf = sm + (kc&1) * BUF_ELEMS;

        #pragma unroll
        for (int ks = 0; ks < 4; ks++) {
            uint32_t ah[2][4], al[2][4];
            #pragma unroll
            for (int mt = 0; mt < 2; mt++) {
                int r0 = wm*32 + mt*16 + gg;
                const __nv_bfloat16* bh = buf + ks*16 + tt*2;
                ah[mt][0] = *(const uint32_t*)(bh + OFF_AH + r0*ASTR);
                ah[mt][1] = *(const uint32_t*)(bh + OFF_AH + (r0+8)*ASTR);
                ah[mt][2] = *(const uint32_t*)(bh + OFF_AH + r0*ASTR + 8);
                ah[mt][3] = *(const uint32_t*)(bh + OFF_AH + (r0+8)*ASTR + 8);
                al[mt][0] = *(const uint32_t*)(bh + OFF_AL + r0*ASTR);
                al[mt][1] = *(const uint32_t*)(bh + OFF_AL + (r0+8)*ASTR);
                al[mt][2] = *(const uint32_t*)(bh + OFF_AL + r0*ASTR + 8);
                al[mt][3] = *(const uint32_t*)(bh + OFF_AL + (r0+8)*ASTR + 8);
            }
            #pragma unroll
            for (int nt = 0; nt < 8; nt++) {
                int n0 = wn*64 + nt*8 + gg;
                const __nv_bfloat16* bb2 = buf + n0*ASTR + ks*16 + tt*2;
                uint32_t bh0 = *(const uint32_t*)(bb2 + OFF_BH);
                uint32_t bh1 = *(const uint32_t*)(bb2 + OFF_BH + 8);
                uint32_t bl0 = *(const uint32_t*)(bb2 + OFF_BL);
                uint32_t bl1 = *(const uint32_t*)(bb2 + OFF_BL + 8);
                #pragma unroll
                for (int mt = 0; mt < 2; mt++) {
                    mma_bf16(acc[mt][nt], ah[mt], bh0, bh1);
                    mma_bf16(acc[mt][nt], al[mt], bh0, bh1);
                    mma_bf16(acc[mt][nt], ah[mt], bl0, bl1);
                }
            }
        }
        __syncthreads();
    }

    #pragma unroll
    for (int mt = 0; mt < 2; mt++) {
        int row = bm*128 + wm*32 + mt*16 + gg;
        #pragma unroll
        for (int nt = 0; nt < 8; nt++) {
            int col = bn*128 + wn*64 + nt*8 + tt*2;
            float2 v0 = {acc[mt][nt][0], acc[mt][nt][1]};
            float2 v1 = {acc[mt][nt][2], acc[mt][nt][3]};
            *(float2*)(C + (size_t)row*HD + col)     = v0;
            *(float2*)(C + (size_t)(row+8)*HD + col) = v1;
        }
    }
}

// ---------------- GCN aggregate + relu (node range; fused dots) -----------
__global__ void __launch_bounds__(256) gcn_agg_kernel(const float* __restrict__ b,
                                                      const float* __restrict__ wg,
                                                      int which, int node0) {
    __shared__ float sred[8];
    __shared__ float sred2[8];
    int tid = threadIdx.x;
    int grp = tid >> 6, lane = tid & 63, wid = tid >> 5;
    int i = node0 + blockIdx.x * 4 + grp;
    int rs = g_rowstart[i], c = g_cnt[i];
    const float4* h4 = (const float4*)g_h;
    float4 acc = {0.f, 0.f, 0.f, 0.f};
    int j = 0;
    for (; j + 4 <= c; j += 4) {
        int   s0 = g_csr[rs+j],   s1 = g_csr[rs+j+1],  s2 = g_csr[rs+j+2],  s3 = g_csr[rs+j+3];
        float w0 = g_csrw[rs+j],  w1 = g_csrw[rs+j+1], w2 = g_csrw[rs+j+2], w3 = g_csrw[rs+j+3];
        float4 x0 = h4[(size_t)s0*64 + lane];
        float4 x1 = h4[(size_t)s1*64 + lane];
        float4 x2 = h4[(size_t)s2*64 + lane];
        float4 x3 = h4[(size_t)s3*64 + lane];
        acc.x = fmaf(x0.x, w0, acc.x); acc.y = fmaf(x0.y, w0, acc.y);
        acc.z = fmaf(x0.z, w0, acc.z); acc.w = fmaf(x0.w, w0, acc.w);
        acc.x = fmaf(x1.x, w1, acc.x); acc.y = fmaf(x1.y, w1, acc.y);
        acc.z = fmaf(x1.z, w1, acc.z); acc.w = fmaf(x1.w, w1, acc.w);
        acc.x = fmaf(x2.x, w2, acc.x); acc.y = fmaf(x2.y, w2, acc.y);
        acc.z = fmaf(x2.z, w2, acc.z); acc.w = fmaf(x2.w, w2, acc.w);
        acc.x = fmaf(x3.x, w3, acc.x); acc.y = fmaf(x3.y, w3, acc.y);
        acc.z = fmaf(x3.z, w3, acc.z); acc.w = fmaf(x3.w, w3, acc.w);
    }
    for (; j < c; j++) {
        int   s0 = g_csr[rs+j];
        float w0 = g_csrw[rs+j];
        float4 x0 = h4[(size_t)s0*64 + lane];
        acc.x = fmaf(x0.x, w0, acc.x); acc.y = fmaf(x0.y, w0, acc.y);
        acc.z = fmaf(x0.z, w0, acc.z); acc.w = fmaf(x0.w, w0, acc.w);
    }
    float sl = 1.0f / g_deg[i];
    float4 xi = h4[(size_t)i*64 + lane];
    float4 bb = ((const float4*)b)[lane];
    float4 v;
    v.x = fmaxf(fmaf(xi.x, sl, acc.x) + bb.x, 0.f);
    v.y = fmaxf(fmaf(xi.y, sl, acc.y) + bb.y, 0.f);
    v.z = fmaxf(fmaf(xi.z, sl, acc.z) + bb.z, 0.f);
    v.w = fmaxf(fmaf(xi.w, sl, acc.w) + bb.w, 0.f);
    ((float4*)g_y)[(size_t)i*64 + lane] = v;
    float4 pn = ((const float4*)(g_pn + which*HD))[lane];
    float4 wg4 = ((const float4*)wg)[lane];
    float s  = v.x*pn.x + v.y*pn.y + v.z*pn.z + v.w*pn.w;
    float s2 = v.x*wg4.x + v.y*wg4.y + v.z*wg4.z + v.w*wg4.w;
    #pragma unroll
    for (int o = 16; o > 0; o >>= 1) {
        s  += __shfl_down_sync(0xffffffffu, s,  o);
        s2 += __shfl_down_sync(0xffffffffu, s2, o);
    }
    if ((tid & 31) == 0) { sred[wid] = s; sred2[wid] = s2; }
    __syncthreads();
    if (tid < 4) {
        int i2 = node0 + blockIdx.x*4 + tid;
        g_score[i2] = sred[2*tid]  + sred[2*tid+1];
        g_ydw[i2]   = sred2[2*tid] + sred2[2*tid+1];
    }
}

// -------- fused top-k + gates + softmax + attention pool (graph range) ----
__global__ void topk_fused_kernel(int n_per, int k, int accumulate, int write_maps,
                                  const float* __restrict__ bg, int g0) {
    __shared__ float sv[512];
    __shared__ int   si[512];
    __shared__ int   sold[256];
    __shared__ float scoef[256];
    __shared__ float rbuf[512];
    int g = g0 + blockIdx.x, tid = threadIdx.x;
    int T = blockDim.x;
    sv[tid] = g_score[g*n_per + tid];
    si[tid] = tid;
    __syncthreads();
    for (int ksz = 2; ksz <= n_per; ksz <<= 1) {
        for (int j = ksz >> 1; j > 0; j >>= 1) {
            int ixj = tid ^ j;
            if (ixj > tid) {
                bool asc = ((tid & ksz) == 0);
                float v1 = sv[tid], v2 = sv[ixj];
                int   i1 = si[tid], i2 = si[ixj];
                bool b12 = (v1 > v2) || (v1 == v2 && i1 < i2);
                if (asc != b12) {
                    sv[tid] = v2; si[tid] = i2;
                    sv[ixj] = v1; si[ixj] = i1;
                }
            }
            __syncthreads();
        }
    }
    float tanhv = 0.f, gate = -1e30f;
    int old = 0;
    if (tid < k) {
        old = g*n_per + si[tid];
        tanhv = tanhf(sv[tid]);
        if (write_maps) {
            int nid = g*k + tid;
            g_nof[old]    = nid;
            g_oldidx[nid] = old;
            g_gatev[nid]  = tanhv;
        }
        sold[tid] = old;
        gate = tanhv * g_ydw[old] + bg[0];
    }
    __syncthreads();
    rbuf[tid] = gate;
    __syncthreads();
    for (int s = T/2; s > 0; s >>= 1) {
        if (tid < s) rbuf[tid] = fmaxf(rbuf[tid], rbuf[tid+s]);
        __syncthreads();
    }
    float mx = rbuf[0];
    __syncthreads();
    float e = (tid < k) ? expf(gate - mx) : 0.f;
    rbuf[tid] = e;
    __syncthreads();
    for (int s = T/2; s > 0; s >>= 1) {
        if (tid < s) rbuf[tid] += rbuf[tid+s];
        __syncthreads();
    }
    float inv = 1.f / rbuf[0];
    if (tid < k) scoef[tid] = e * inv * tanhv;
    __syncthreads();
    int f = tid & 255;
    int i0 = 0, i1 = k;
    if (T == 512) { if (tid < 256) i1 = k/2; else i0 = k/2; }
    float acc = 0.f;
    for (int i = i0; i < i1; i++)
        acc = fmaf(scoef[i], g_y[(size_t)sold[i]*HD + f], acc);
    if (T == 512) {
        rbuf[tid] = acc;
        __syncthreads();
        if (tid < 256) {
            float tot = rbuf[tid] + rbuf[tid+256];
            if (accumulate) g_out[g*HD + f] += tot;
            else            g_out[g*HD + f]  = tot;
        }
    } else {
        if (accumulate) g_out[g*HD + f] += acc;
        else            g_out[g*HD + f]  = acc;
    }
}

// ---------------- pooled gather (node range) ----------------
__global__ void __launch_bounds__(256) pool_gather_kernel(int nid0) {
    int tid = threadIdx.x;
    int grp = tid >> 6, lane = tid & 63;
    int nid = nid0 + blockIdx.x * 4 + grp;
    int old = g_oldidx[nid];
    float gv = g_gatev[nid];
    float4 v = ((const float4*)g_y)[(size_t)old*64 + lane];
    v.x *= gv; v.y *= gv; v.z *= gv; v.w *= gv;
    size_t o = (size_t)nid*64 + lane;
    uint2 hi, lo;
    split4(v, hi, lo);
    ((uint2*)g_xhi)[o] = hi;
    ((uint2*)g_xlo)[o] = lo;
}

// ---------------- projection head ----------------
__global__ void head_kernel(const float* __restrict__ Wp1, const float* __restrict__ bp1,
                            const float* __restrict__ Wp2, const float* __restrict__ bp2,
                            float* __restrict__ out) {
    __shared__ float o[HD];
    __shared__ float hs[PD];
    __shared__ float lg[PD];
    __shared__ float red[PD];
    int g = blockIdx.x, tid = threadIdx.x;
    o[tid] = g_out[g*HD + tid];
    __syncthreads();
    if (tid < PD) {
        float s = bp1[tid];
        for (int kk = 0; kk < HD; kk++) s = fmaf(o[kk], Wp1[kk*PD + tid], s);
        hs[tid] = fmaxf(s, 0.f);
    }
    __syncthreads();
    if (tid < PD) {
        float s = bp2[tid];
        for (int kk = 0; kk < PD; kk++) s = fmaf(hs[kk], Wp2[kk*PD + tid], s);
        lg[tid] = s;
        red[tid] = s * s;
    }
    __syncthreads();
    for (int s = 64; s > 0; s >>= 1) {
        if (tid < s) red[tid] += red[tid+s];
        __syncthreads();
    }
    float nrm = fmaxf(sqrtf(red[0]), 1e-12f);
    if (tid < PD) out[g*PD + tid] = lg[tid] / nrm;
    out[BG*PD + g*HD + tid] = o[tid];
}

// ---------------- driver: two half-pipelines (graphs 0-31 / 32-63) -------
extern "C" void kernel_launch(void* const* d_in, const int* in_sizes, int n_in,
                              void* d_out, int out_size) {
    const int*   tokens = (const int*)  d_in[0];
    const int*   src    = (const int*)  d_in[1];
    const int*   dst    = (const int*)  d_in[2];
    const float* eattr  = (const float*)d_in[3];
    const float* emb    = (const float*)d_in[4];
    const float* W0     = (const float*)d_in[5];
    const float* b0     = (const float*)d_in[6];
    const float* W1     = (const float*)d_in[7];
    const float* b1     = (const float*)d_in[8];
    const float* p0     = (const float*)d_in[9];
    const float* p1     = (const float*)d_in[10];
    const float* wg     = (const float*)d_in[11];
    const float* bg     = (const float*)d_in[12];
    const float* Wp1    = (const float*)d_in[13];
    const float* bp1    = (const float*)d_in[14];
    const float* Wp2    = (const float*)d_in[15];
    const float* bp2    = (const float*)d_in[16];
    float* out = (float*)d_out;

    cudaFuncSetAttribute(gemm_mma_kernel, cudaFuncAttributeMaxDynamicSharedMemorySize, GEMM_SMEM);

    float* gh_dev = nullptr; cudaGetSymbolAddress((void**)&gh_dev, g_h);

    cudaStream_t s2;
    cudaStreamCreateWithFlags(&s2, cudaStreamNonBlocking);
    cudaEvent_t ev_fork, ev_w, ev_mid, ev_s2end;
    cudaEventCreateWithFlags(&ev_fork,  cudaEventDisableTiming);
    cudaEventCreateWithFlags(&ev_w,     cudaEventDisableTiming);
    cudaEventCreateWithFlags(&ev_mid,   cudaEventDisableTiming);
    cudaEventCreateWithFlags(&ev_s2end, cudaEventDisableTiming);

    const int HB = BG/2;          // 32 graphs per half
    cudaEventRecord(ev_fork, 0);
    cudaStreamWaitEvent(s2, ev_fork, 0);

    // ---- s2 prelude: weights (needed by both halves) ----
    wsplit_kernel<<<512, 256, 0, s2>>>(W0, W1);
    normp_kernel<<<2, HD, 0, s2>>>(p0, p1);
    cudaEventRecord(ev_w, s2);

    // ======== half A pipeline (graphs 0..31) on main ========
    st_encode_kernel<<<NN/8, 256>>>(tokens, emb, 0);
    edge_build1_kernel<<<HB, 1024>>>(eattr, src, dst, 0);
    cudaStreamWaitEvent(0, ev_w, 0);
    gemm_mma_kernel<<<dim3(NN/256, 2), 256, GEMM_SMEM>>>(0, 0, gh_dev);
    gcn_agg_kernel<<<NN/8, 256>>>(b0, wg, 0, 0);
    topk_fused_kernel<<<HB, NPG>>>(NPG, KP1, 0, 1, bg, 0);
    pool_gather_kernel<<<N2/8, 256>>>(0);
    cudaEventRecord(ev_mid, 0);
    edge_build2_kernel<<<HB, 1024>>>(src, dst, 0);
    gemm_mma_kernel<<<dim3(N2/256, 2), 256, GEMM_SMEM>>>(1, 0, gh_dev);
    gcn_agg_kernel<<<N2/8, 256>>>(b1, wg, 1, 0);
    topk_fused_kernel<<<HB, KP1>>>(KP1, KP2, 1, 0, bg, 0);

    // ======== half B pipeline (graphs 32..63) on s2 ========
    st_encode_kernel<<<NN/8, 256, 0, s2>>>(tokens, emb, NN/2);
    edge_build1_kernel<<<HB, 1024, 0, s2>>>(eattr, src, dst, HB);
    gemm_mma_kernel<<<dim3(NN/256, 2), 256, GEMM_SMEM, s2>>>(0, NN/256, gh_dev);
    gcn_agg_kernel<<<NN/8, 256, 0, s2>>>(b0, wg, 0, NN/2);
    topk_fused_kernel<<<HB, NPG, 0, s2>>>(NPG, KP1, 0, 1, bg, HB);
    // half-B layer-2 writes alias half-A layer-1 regions: wait for half-A
    // to finish all its layer-1 readers (gemmA/aggA/topkA/gatherA).
    cudaStreamWaitEvent(s2, ev_mid, 0);
    pool_gather_kernel<<<N2/8, 256, 0, s2>>>(N2/2);
    edge_build2_kernel<<<HB, 1024, 0, s2>>>(src, dst, HB);
    gemm_mma_kernel<<<dim3(N2/256, 2), 256, GEMM_SMEM, s2>>>(1, N2/256, gh_dev);
    gcn_agg_kernel<<<N2/8, 256, 0, s2>>>(b1, wg, 1, N2/2);
    topk_fused_kernel<<<HB, KP1, 0, s2>>>(KP1, KP2, 1, 0, bg, HB);
    cudaEventRecord(ev_s2end, s2);

    // ---- join + head ----
    cudaStreamWaitEvent(0, ev_s2end, 0);
    head_kernel<<<BG, 256>>>(Wp1, bp1, Wp2, bp2, out);
}

// round 13
// speedup vs baseline: 1.0063x; 1.0063x over previous
#include <cuda_runtime.h>
#include <cuda_bf16.h>
#include <cstdint>

// ---------------- static problem config ----------------
#define BG   64
#define NPG  512
#define NN   (BG*NPG)     // 32768
#define EPG  8192
#define EE   (BG*EPG)     // 524288
#define LTOK 16
#define HD   256
#define PD   128
#define KP1  256
#define KP2  128
#define N2   (BG*KP1)     // 16384

// ---------------- device scratch ----------------
__device__ float g_w[EE];
__device__ float g_h[NN*HD];
__device__ float g_y[NN*HD];
__device__ __nv_bfloat16 g_xhi[NN*HD];
__device__ __nv_bfloat16 g_xlo[NN*HD];
__device__ float g_deg[NN];
__device__ float g_score[NN];
__device__ float g_ydw[NN];
__device__ float g_gatev[NN];
__device__ int   g_cnt[NN];
__device__ int   g_rowstart[NN];
__device__ int   g_csr[EE];
__device__ float g_csrw[EE];
__device__ int   g_nof[NN];
__device__ int   g_oldidx[NN];
__device__ float g_out[BG*HD];
__device__ float g_pn[2*HD];
__device__ __nv_bfloat16 g_WThi[2][HD*HD];
__device__ __nv_bfloat16 g_WTlo[2][HD*HD];

// ---------------- helpers ----------------
__device__ __forceinline__ uint32_t smem_u32(const void* p) {
    uint32_t a;
    asm("{ .reg .u64 t; cvta.to.shared.u64 t, %1; cvt.u32.u64 %0, t; }" : "=r"(a) : "l"(p));
    return a;
}
__device__ __forceinline__ void cp_async16(uint32_t dst, const void* src) {
    asm volatile("cp.async.ca.shared.global [%0], [%1], 16;" :: "r"(dst), "l"(src) : "memory");
}
#define CP_COMMIT() asm volatile("cp.async.commit_group;" ::: "memory")
#define CP_WAIT(n)  asm volatile("cp.async.wait_group %0;" :: "n"(n) : "memory")

__device__ __forceinline__ void split4(float4 v, uint2& hi, uint2& lo) {
    __nv_bfloat162 h0 = __floats2bfloat162_rn(v.x, v.y);
    __nv_bfloat162 h1 = __floats2bfloat162_rn(v.z, v.w);
    float rx = v.x - __bfloat162float(__low2bfloat16(h0));
    float ry = v.y - __bfloat162float(__high2bfloat16(h0));
    float rz = v.z - __bfloat162float(__low2bfloat16(h1));
    float rw = v.w - __bfloat162float(__high2bfloat16(h1));
    __nv_bfloat162 l0 = __floats2bfloat162_rn(rx, ry);
    __nv_bfloat162 l1 = __floats2bfloat162_rn(rz, rw);
    hi = make_uint2(*(uint32_t*)&h0, *(uint32_t*)&h1);
    lo = make_uint2(*(uint32_t*)&l0, *(uint32_t*)&l1);
}

// ---------------- ST encoder (node-range; fused nof=-1) -------------------
__global__ void __launch_bounds__(256) st_encode_kernel(const int* __restrict__ tokens,
                                                        const float* __restrict__ emb,
                                                        int node0) {
    int tid = threadIdx.x;
    int grp = tid >> 6, lane = tid & 63;
    int nbase = node0 + blockIdx.x * 4;
    int node = nbase + grp;
    __shared__ int toks[4*LTOK];
    if (tid < 4*LTOK) toks[tid] = tokens[nbase*LTOK + tid];
    if (lane == 0) g_nof[node] = -1;
    __syncthreads();
    const float4* emb4 = (const float4*)emb;
    float4 acc = {0.f, 0.f, 0.f, 0.f};
    int cnt = 0;
    #pragma unroll
    for (int l = 0; l < LTOK; l++) {
        int t = toks[grp*LTOK + l];
        if (t != 0) {
            float4 v = emb4[(size_t)t*64 + lane];
            acc.x += v.x; acc.y += v.y; acc.z += v.z; acc.w += v.w;
            cnt++;
        }
    }
    float inv = 1.f / (float)(cnt > 0 ? cnt : 1);
    acc.x *= inv; acc.y *= inv; acc.z *= inv; acc.w *= inv;
    size_t o = (size_t)node*64 + lane;
    uint2 hi, lo;
    split4(acc, hi, lo);
    ((uint2*)g_xhi)[o] = hi;
    ((uint2*)g_xlo)[o] = lo;
}

// ---------------- W^T bf16 split ----------------
__global__ void wsplit_kernel(const float* __restrict__ W0, const float* __restrict__ W1) {
    int b = blockIdx.x;
    int which = b >> 8, k = b & 255, n = threadIdx.x;
    const float* W = which ? W1 : W0;
    float v = W[k*HD + n];
    __nv_bfloat16 hi = __float2bfloat16(v);
    float lo = v - __bfloat162float(hi);
    g_WThi[which][n*HD + k] = hi;
    g_WTlo[which][n*HD + k] = __float2bfloat16(lo);
}

// ---------------- normalized p0,p1 ----------------
__global__ void normp_kernel(const float* __restrict__ p0, const float* __restrict__ p1) {
    __shared__ float red[HD];
    int which = blockIdx.x, tid = threadIdx.x;
    const float* p = which ? p1 : p0;
    float v = p[tid];
    red[tid] = v*v; __syncthreads();
    for (int s = HD/2; s > 0; s >>= 1) {
        if (tid < s) red[tid] += red[tid+s];
        __syncthreads();
    }
    g_pn[which*HD + tid] = v / sqrtf(red[0]);
}

// ======== fused edge pipeline, layer 1 =========
__global__ void __launch_bounds__(1024) edge_build1_kernel(const float* __restrict__ ea,
                                                           const int* __restrict__ src,
                                                           const int* __restrict__ dst) {
    __shared__ float sdeg[NPG];
    __shared__ int   scnt[NPG];
    __shared__ float sdinv[NPG];
    __shared__ int   scur[NPG];
    __shared__ int   sscan[NPG];
    int g = blockIdx.x, tid = threadIdx.x;
    int ebase = g * EPG;
    if (tid < NPG) { sdeg[tid] = 1.0f; scnt[tid] = 0; }
    __syncthreads();
    #pragma unroll
    for (int k = 0; k < EPG/1024; k++) {
        int e = ebase + k*1024 + tid;
        float w = 0.5f * (ea[2*e] + ea[2*e+1]);
        g_w[e] = w;
        int dl = dst[e] - g*NPG;
        atomicAdd(&sdeg[dl], w);
        atomicAdd(&scnt[dl], 1);
    }
    __syncthreads();
    int c = 0;
    if (tid < NPG) {
        int node = g*NPG + tid;
        float dg = sdeg[tid];
        c = scnt[tid];
        sdinv[tid] = rsqrtf(dg);
        g_deg[node] = dg;
        g_cnt[node] = c;
        sscan[tid] = c;
    }
    __syncthreads();
    for (int off = 1; off < NPG; off <<= 1) {
        int v = (tid >= off && tid < NPG) ? sscan[tid-off] : 0;
        __syncthreads();
        if (tid < NPG) sscan[tid] += v;
        __syncthreads();
    }
    if (tid < NPG) {
        int rs = ebase + sscan[tid] - c;
        g_rowstart[g*NPG + tid] = rs;
        scur[tid] = rs;
    }
    __syncthreads();
    #pragma unroll
    for (int k = 0; k < EPG/1024; k++) {
        int e = ebase + k*1024 + tid;
        int sl = src[e] - g*NPG;
        int dl = dst[e] - g*NPG;
        float w = g_w[e];
        int pos = atomicAdd(&scur[dl], 1);
        g_csr[pos]  = g*NPG + sl;
        g_csrw[pos] = sdinv[sl] * w * sdinv[dl];
    }
}

// ======== fused edge pipeline, layer 2 ======
__global__ void __launch_bounds__(1024) edge_build2_kernel(const int* __restrict__ src,
                                                           const int* __restrict__ dst) {
    __shared__ float sdeg[KP1];
    __shared__ int   scnt[KP1];
    __shared__ float sdinv[KP1];
    __shared__ int   scur[KP1];
    __shared__ int   sscan[KP1];
    int g = blockIdx.x, tid = threadIdx.x;
    int ebase = g * EPG;
    if (tid < KP1) { sdeg[tid] = 1.0f; scnt[tid] = 0; }
    __syncthreads();
    #pragma unroll
    for (int k = 0; k < EPG/1024; k++) {
        int e = ebase + k*1024 + tid;
        int ns = g_nof[src[e]], nd = g_nof[dst[e]];
        if (ns >= 0 && nd >= 0) {
            float w = g_w[e];
            int dl = nd - g*KP1;
            atomicAdd(&sdeg[dl], w);
            atomicAdd(&scnt[dl], 1);
        }
    }
    __syncthreads();
    int c = 0;
    if (tid < KP1) {
        int node = g*KP1 + tid;
        float dg = sdeg[tid];
        c = scnt[tid];
        sdinv[tid] = rsqrtf(dg);
        g_deg[node] = dg;
        g_cnt[node] = c;
        sscan[tid] = c;
    }
    __syncthreads();
    for (int off = 1; off < KP1; off <<= 1) {
        int v = (tid >= off && tid < KP1) ? sscan[tid-off] : 0;
        __syncthreads();
        if (tid < KP1) sscan[tid] += v;
        __syncthreads();
    }
    if (tid < KP1) {
        int rs = ebase + sscan[tid] - c;
        g_rowstart[g*KP1 + tid] = rs;
        scur[tid] = rs;
    }
    __syncthreads();
    #pragma unroll
    for (int k = 0; k < EPG/1024; k++) {
        int e = ebase + k*1024 + tid;
        int ns = g_nof[src[e]], nd = g_nof[dst[e]];
        if (ns >= 0 && nd >= 0) {
            float w = g_w[e];
            int sl = ns - g*KP1, dl = nd - g*KP1;
            int pos = atomicAdd(&scur[dl], 1);
            g_csr[pos]  = ns;
            g_csrw[pos] = sdinv[sl] * w * sdinv[dl];
        }
    }
}

// ================= GEMM common =================
#define ASTR 72
#define OFF_AH 0
#define OFF_AL (128*ASTR)
#define OFF_BH (2*128*ASTR)
#define OFF_BL (3*128*ASTR)
#define BUF_ELEMS (4*128*ASTR)
#define GEMM_SMEM (2*BUF_ELEMS*2)

__device__ __forceinline__ void mma_bf16(float* c, const uint32_t* a,
                                         uint32_t b0, uint32_t b1) {
    asm volatile(
        "mma.sync.aligned.m16n8k16.row.col.f32.bf16.bf16.f32 "
        "{%0,%1,%2,%3},{%4,%5,%6,%7},{%8,%9},{%0,%1,%2,%3};"
        : "+f"(c[0]), "+f"(c[1]), "+f"(c[2]), "+f"(c[3])
        : "r"(a[0]), "r"(a[1]), "r"(a[2]), "r"(a[3]), "r"(b0), "r"(b1));
}

__device__ __forceinline__ void gemm_compute_chunk(const __nv_bfloat16* buf,
                                                   float acc[2][8][4],
                                                   int wm, int wn, int gg, int tt) {
    #pragma unroll
    for (int ks = 0; ks < 4; ks++) {
        uint32_t ah[2][4], al[2][4];
        #pragma unroll
        for (int mt = 0; mt < 2; mt++) {
            int r0 = wm*32 + mt*16 + gg;
            const __nv_bfloat16* bh = buf + ks*16 + tt*2;
            ah[mt][0] = *(const uint32_t*)(bh + OFF_AH + r0*ASTR);
            ah[mt][1] = *(const uint32_t*)(bh + OFF_AH + (r0+8)*ASTR);
            ah[mt][2] = *(const uint32_t*)(bh + OFF_AH + r0*ASTR + 8);
            ah[mt][3] = *(const uint32_t*)(bh + OFF_AH + (r0+8)*ASTR + 8);
            al[mt][0] = *(const uint32_t*)(bh + OFF_AL + r0*ASTR);
            al[mt][1] = *(const uint32_t*)(bh + OFF_AL + (r0+8)*ASTR);
            al[mt][2] = *(const uint32_t*)(bh + OFF_AL + r0*ASTR + 8);
            al[mt][3] = *(const uint32_t*)(bh + OFF_AL + (r0+8)*ASTR + 8);
        }
        #pragma unroll
        for (int nt = 0; nt < 8; nt++) {
            int n0 = wn*64 + nt*8 + gg;
            const __nv_bfloat16* bb2 = buf + n0*ASTR + ks*16 + tt*2;
            uint32_t bh0 = *(const uint32_t*)(bb2 + OFF_BH);
            uint32_t bh1 = *(const uint32_t*)(bb2 + OFF_BH + 8);
            uint32_t bl0 = *(const uint32_t*)(bb2 + OFF_BL);
            uint32_t bl1 = *(const uint32_t*)(bb2 + OFF_BL + 8);
            #pragma unroll
            for (int mt = 0; mt < 2; mt++) {
                mma_bf16(acc[mt][nt], ah[mt], bh0, bh1);
                mma_bf16(acc[mt][nt], al[mt], bh0, bh1);
                mma_bf16(acc[mt][nt], ah[mt], bl0, bl1);
            }
        }
    }
}

__device__ __forceinline__ void gemm_epilogue(float acc[2][8][4], float* C,
                                              int bm, int bn, int wm, int wn,
                                              int gg, int tt) {
    #pragma unroll
    for (int mt = 0; mt < 2; mt++) {
        int row = bm*128 + wm*32 + mt*16 + gg;
        #pragma unroll
        for (int nt = 0; nt < 8; nt++) {
            int col = bn*128 + wn*64 + nt*8 + tt*2;
            float2 v0 = {acc[mt][nt][0], acc[mt][nt][1]};
            float2 v1 = {acc[mt][nt][2], acc[mt][nt][3]};
            *(float2*)(C + (size_t)row*HD + col)     = v0;
            *(float2*)(C + (size_t)(row+8)*HD + col) = v1;
        }
    }
}

// ---- layer-1 GEMM: A from pre-split xhi/xlo, fully cp.async ----
__global__ void __launch_bounds__(256, 1) gemm_mma_kernel(int which, int bm0,
                                                          float* __restrict__ C) {
    extern __shared__ __align__(16) __nv_bfloat16 sm[];
    int tid = threadIdx.x;
    int bm = bm0 + blockIdx.x, bn = blockIdx.y;
    int warp = tid >> 5, lane = tid & 31;
    int wm = warp >> 1, wn = warp & 1;
    int gg = lane >> 2, tt = lane & 3;

    const __nv_bfloat16* Ah = g_xhi + (size_t)(bm*128) * HD;
    const __nv_bfloat16* Al = g_xlo + (size_t)(bm*128) * HD;
    const __nv_bfloat16* Bh = g_WThi[which] + (size_t)(bn*128) * HD;
    const __nv_bfloat16* Bl = g_WTlo[which] + (size_t)(bn*128) * HD;
    uint32_t sbase = smem_u32(sm);

    float acc[2][8][4];
    #pragma unroll
    for (int mt = 0; mt < 2; mt++)
        #pragma unroll
        for (int nt = 0; nt < 8; nt++)
            #pragma unroll
            for (int q = 0; q < 4; q++) acc[mt][nt][q] = 0.f;

    auto issue = [&](int kc, int buf) {
        uint32_t bb = sbase + buf * (BUF_ELEMS*2);
        #pragma unroll
        for (int it = 0; it < 4; it++) {
            int u = it*256 + tid;
            int row = u >> 3, seg = u & 7;
            size_t go = (size_t)row*HD + kc*64 + seg*8;
            uint32_t so = (row*ASTR + seg*8) * 2;
            cp_async16(bb + OFF_AH*2 + so, Ah + go);
            cp_async16(bb + OFF_AL*2 + so, Al + go);
            cp_async16(bb + OFF_BH*2 + so, Bh + go);
            cp_async16(bb + OFF_BL*2 + so, Bl + go);
        }
        CP_COMMIT();
    };

    issue(0, 0);
    #pragma unroll
    for (int kc = 0; kc < 4; kc++) {
        if (kc < 3) { issue(kc+1, (kc+1)&1); CP_WAIT(1); }
        else        { CP_WAIT(0); }
        __syncthreads();
        gemm_compute_chunk(sm + (kc&1)*BUF_ELEMS, acc, wm, wn, gg, tt);
        __syncthreads();
    }
    gemm_epilogue(acc, C, bm, bn, wm, wn, gg, tt);
}

// ---- layer-2 GEMM: A gathered from g_y via oldidx/gatev, split on the fly --
__global__ void __launch_bounds__(256, 1) gemm2_gather_kernel(float* __restrict__ C) {
    extern __shared__ __align__(16) __nv_bfloat16 sm[];
    int tid = threadIdx.x;
    int bm = blockIdx.x, bn = blockIdx.y;
    int warp = tid >> 5, lane = tid & 31;
    int wm = warp >> 1, wn = warp & 1;
    int gg = lane >> 2, tt = lane & 3;

    const __nv_bfloat16* Bh = g_WThi[1] + (size_t)(bn*128) * HD;
    const __nv_bfloat16* Bl = g_WTlo[1] + (size_t)(bn*128) * HD;
    uint32_t sbase = smem_u32(sm);

    float acc[2][8][4];
    #pragma unroll
    for (int mt = 0; mt < 2; mt++)
        #pragma unroll
        for (int nt = 0; nt < 8; nt++)
            #pragma unroll
            for (int q = 0; q < 4; q++) acc[mt][nt][q] = 0.f;

    auto issueB = [&](int kc, int buf) {
        uint32_t bb = sbase + buf * (BUF_ELEMS*2);
        #pragma unroll
        for (int it = 0; it < 4; it++) {
            int u = it*256 + tid;
            int row = u >> 3, seg = u & 7;
            size_t go = (size_t)row*HD + kc*64 + seg*8;
            uint32_t so = (row*ASTR + seg*8) * 2;
            cp_async16(bb + OFF_BH*2 + so, Bh + go);
            cp_async16(bb + OFF_BL*2 + so, Bl + go);
        }
        CP_COMMIT();
    };
    auto stageA = [&](int kc, int buf) {
        __nv_bfloat16* dst = sm + buf * BUF_ELEMS;
        #pragma unroll
        for (int it = 0; it < 4; it++) {
            int u = it*256 + tid;
            int row = u >> 3, seg = u & 7;
            int nid = bm*128 + row;
            int old = g_oldidx[nid];
            float gv = g_gatev[nid];
            const float4* yp = (const float4*)(g_y + (size_t)old*HD + kc*64 + seg*8);
            float4 v0 = yp[0], v1 = yp[1];
            v0.x *= gv; v0.y *= gv; v0.z *= gv; v0.w *= gv;
            v1.x *= gv; v1.y *= gv; v1.z *= gv; v1.w *= gv;
            uint2 h0, l0, h1, l1;
            split4(v0, h0, l0);
            split4(v1, h1, l1);
            int so = row*ASTR + seg*8;
            *(uint2*)(dst + OFF_AH + so)     = h0;
            *(uint2*)(dst + OFF_AH + so + 4) = h1;
            *(uint2*)(dst + OFF_AL + so)     = l0;
            *(uint2*)(dst + OFF_AL + so + 4) = l1;
        }
    };

    issueB(0, 0);
    stageA(0, 0);
    #pragma unroll
    for (int kc = 0; kc < 4; kc++) {
        if (kc < 3) {
            issueB(kc+1, (kc+1)&1);
            stageA(kc+1, (kc+1)&1);
            CP_WAIT(1);
        } else {
            CP_WAIT(0);
        }
        __syncthreads();
        gemm_compute_chunk(sm + (kc&1)*BUF_ELEMS, acc, wm, wn, gg, tt);
        __syncthreads();
    }
    gemm_epilogue(acc, C, bm, bn, wm, wn, gg, tt);
}

// ---------------- GCN aggregate + relu (fused: score dot + wg dot) --------
__global__ void __launch_bounds__(256) gcn_agg_kernel(const float* __restrict__ b,
                                                      const float* __restrict__ wg,
                                                      int which) {
    __shared__ float sred[8];
    __shared__ float sred2[8];
    int tid = threadIdx.x;
    int grp = tid >> 6, lane = tid & 63, wid = tid >> 5;
    int i = blockIdx.x * 4 + grp;
    int rs = g_rowstart[i], c = g_cnt[i];
    const float4* h4 = (const float4*)g_h;
    float4 acc = {0.f, 0.f, 0.f, 0.f};
    int j = 0;
    for (; j + 4 <= c; j += 4) {
        int   s0 = g_csr[rs+j],   s1 = g_csr[rs+j+1],  s2 = g_csr[rs+j+2],  s3 = g_csr[rs+j+3];
        float w0 = g_csrw[rs+j],  w1 = g_csrw[rs+j+1], w2 = g_csrw[rs+j+2], w3 = g_csrw[rs+j+3];
        float4 x0 = h4[(size_t)s0*64 + lane];
        float4 x1 = h4[(size_t)s1*64 + lane];
        float4 x2 = h4[(size_t)s2*64 + lane];
        float4 x3 = h4[(size_t)s3*64 + lane];
        acc.x = fmaf(x0.x, w0, acc.x); acc.y = fmaf(x0.y, w0, acc.y);
        acc.z = fmaf(x0.z, w0, acc.z); acc.w = fmaf(x0.w, w0, acc.w);
        acc.x = fmaf(x1.x, w1, acc.x); acc.y = fmaf(x1.y, w1, acc.y);
        acc.z = fmaf(x1.z, w1, acc.z); acc.w = fmaf(x1.w, w1, acc.w);
        acc.x = fmaf(x2.x, w2, acc.x); acc.y = fmaf(x2.y, w2, acc.y);
        acc.z = fmaf(x2.z, w2, acc.z); acc.w = fmaf(x2.w, w2, acc.w);
        acc.x = fmaf(x3.x, w3, acc.x); acc.y = fmaf(x3.y, w3, acc.y);
        acc.z = fmaf(x3.z, w3, acc.z); acc.w = fmaf(x3.w, w3, acc.w);
    }
    for (; j < c; j++) {
        int   s0 = g_csr[rs+j];
        float w0 = g_csrw[rs+j];
        float4 x0 = h4[(size_t)s0*64 + lane];
        acc.x = fmaf(x0.x, w0, acc.x); acc.y = fmaf(x0.y, w0, acc.y);
        acc.z = fmaf(x0.z, w0, acc.z); acc.w = fmaf(x0.w, w0, acc.w);
    }
    float sl = 1.0f / g_deg[i];
    float4 xi = h4[(size_t)i*64 + lane];
    float4 bb = ((const float4*)b)[lane];
    float4 v;
    v.x = fmaxf(fmaf(xi.x, sl, acc.x) + bb.x, 0.f);
    v.y = fmaxf(fmaf(xi.y, sl, acc.y) + bb.y, 0.f);
    v.z = fmaxf(fmaf(xi.z, sl, acc.z) + bb.z, 0.f);
    v.w = fmaxf(fmaf(xi.w, sl, acc.w) + bb.w, 0.f);
    ((float4*)g_y)[(size_t)i*64 + lane] = v;
    float4 pn = ((const float4*)(g_pn + which*HD))[lane];
    float4 wg4 = ((const float4*)wg)[lane];
    float s  = v.x*pn.x + v.y*pn.y + v.z*pn.z + v.w*pn.w;
    float s2 = v.x*wg4.x + v.y*wg4.y + v.z*wg4.z + v.w*wg4.w;
    #pragma unroll
    for (int o = 16; o > 0; o >>= 1) {
        s  += __shfl_down_sync(0xffffffffu, s,  o);
        s2 += __shfl_down_sync(0xffffffffu, s2, o);
    }
    if ((tid & 31) == 0) { sred[wid] = s; sred2[wid] = s2; }
    __syncthreads();
    if (tid < 4) {
        int i2 = blockIdx.x*4 + tid;
        g_score[i2] = sred[2*tid]  + sred[2*tid+1];
        g_ydw[i2]   = sred2[2*tid] + sred2[2*tid+1];
    }
}

// -------- layer-1 fused top-k + gates + softmax + attention pool ----------
__global__ void topk1_fused_kernel(const float* __restrict__ bg) {
    __shared__ float sv[512];
    __shared__ int   si[512];
    __shared__ int   sold[256];
    __shared__ float scoef[256];
    __shared__ float rbuf[512];
    const int n_per = NPG, k = KP1;
    int g = blockIdx.x, tid = threadIdx.x;
    sv[tid] = g_score[g*n_per + tid];
    si[tid] = tid;
    __syncthreads();
    for (int ksz = 2; ksz <= n_per; ksz <<= 1) {
        for (int j = ksz >> 1; j > 0; j >>= 1) {
            int ixj = tid ^ j;
            if (ixj > tid) {
                bool asc = ((tid & ksz) == 0);
                float v1 = sv[tid], v2 = sv[ixj];
                int   i1 = si[tid], i2 = si[ixj];
                bool b12 = (v1 > v2) || (v1 == v2 && i1 < i2);
                if (asc != b12) {
                    sv[tid] = v2; si[tid] = i2;
                    sv[ixj] = v1; si[ixj] = i1;
                }
            }
            __syncthreads();
        }
    }
    float tanhv = 0.f, gate = -1e30f;
    int old = 0;
    if (tid < k) {
        old = g*n_per + si[tid];
        tanhv = tanhf(sv[tid]);
        int nid = g*k + tid;
        g_nof[old]    = nid;
        g_oldidx[nid] = old;
        g_gatev[nid]  = tanhv;
        sold[tid] = old;
        gate = tanhv * g_ydw[old] + bg[0];
    }
    __syncthreads();
    rbuf[tid] = gate;
    __syncthreads();
    for (int s = 256; s > 0; s >>= 1) {
        if (tid < s) rbuf[tid] = fmaxf(rbuf[tid], rbuf[tid+s]);
        __syncthreads();
    }
    float mx = rbuf[0];
    __syncthreads();
    float e = (tid < k) ? expf(gate - mx) : 0.f;
    rbuf[tid] = e;
    __syncthreads();
    for (int s = 256; s > 0; s >>= 1) {
        if (tid < s) rbuf[tid] += rbuf[tid+s];
        __syncthreads();
    }
    float inv = 1.f / rbuf[0];
    if (tid < k) scoef[tid] = e * inv * tanhv;
    __syncthreads();
    int f = tid & 255;
    int i0 = (tid < 256) ? 0 : k/2;
    int i1 = (tid < 256) ? k/2 : k;
    float acc = 0.f;
    for (int i = i0; i < i1; i++)
        acc = fmaf(scoef[i], g_y[(size_t)sold[i]*HD + f], acc);
    rbuf[tid] = acc;
    __syncthreads();
    if (tid < 256) g_out[g*HD + f] = rbuf[tid] + rbuf[tid+256];
}

// -------- layer-2 fused top-k + attention pool + projection head ----------
__global__ void topk2_head_kernel(const float* __restrict__ bg,
                                  const float* __restrict__ Wp1,
                                  const float* __restrict__ bp1,
                                  const float* __restrict__ Wp2,
                                  const float* __restrict__ bp2,
                                  float* __restrict__ out) {
    __shared__ float sv[256];
    __shared__ int   si[256];
    __shared__ int   sold[128];
    __shared__ float scoef[128];
    __shared__ float rbuf[256];
    __shared__ float o[HD];
    __shared__ float hs[PD];
    __shared__ float lg[PD];
    const int n_per = KP1, k = KP2;
    int g = blockIdx.x, tid = threadIdx.x;
    sv[tid] = g_score[g*n_per + tid];
    si[tid] = tid;
    __syncthreads();
    for (int ksz = 2; ksz <= n_per; ksz <<= 1) {
        for (int j = ksz >> 1; j > 0; j >>= 1) {
            int ixj = tid ^ j;
            if (ixj > tid) {
                bool asc = ((tid & ksz) == 0);
                float v1 = sv[tid], v2 = sv[ixj];
                int   i1 = si[tid], i2 = si[ixj];
                bool b12 = (v1 > v2) || (v1 == v2 && i1 < i2);
                if (asc != b12) {
                    sv[tid] = v2; si[tid] = i2;
                    sv[ixj] = v1; si[ixj] = i1;
                }
            }
            __syncthreads();
        }
    }
    float tanhv = 0.f, gate = -1e30f;
    int old = 0;
    if (tid < k) {
        old = g*n_per + si[tid];
        tanhv = tanhf(sv[tid]);
        sold[tid] = old;
        gate = tanhv * g_ydw[old] + bg[0];
    }
    __syncthreads();
    rbuf[tid] = gate;
    __syncthreads();
    for (int s = 128; s > 0; s >>= 1) {
        if (tid < s) rbuf[tid] = fmaxf(rbuf[tid], rbuf[tid+s]);
        __syncthreads();
    }
    float mx = rbuf[0];
    __syncthreads();
    float e = (tid < k) ? expf(gate - mx) : 0.f;
    rbuf[tid] = e;
    __syncthreads();
    for (int s = 128; s > 0; s >>= 1) {
        if (tid < s) rbuf[tid] += rbuf[tid+s];
        __syncthreads();
    }
    float inv = 1.f / rbuf[0];
    if (tid < k) scoef[tid] = e * inv * tanhv;
    __syncthreads();
    float acc = 0.f;
    for (int i = 0; i < k; i++)
        acc = fmaf(scoef[i], g_y[(size_t)sold[i]*HD + tid], acc);
    o[tid] = g_out[g*HD + tid] + acc;
    __syncthreads();
    if (tid < PD) {
        float s = bp1[tid];
        for (int kk = 0; kk < HD; kk++) s = fmaf(o[kk], Wp1[kk*PD + tid], s);
        hs[tid] = fmaxf(s, 0.f);
    }
    __syncthreads();
    if (tid < PD) {
        float s = bp2[tid];
        for (int kk = 0; kk < PD; kk++) s = fmaf(hs[kk], Wp2[kk*PD + tid], s);
        lg[tid] = s;
        rbuf[tid] = s * s;
    }
    __syncthreads();
    for (int s = 64; s > 0; s >>= 1) {
        if (tid < s) rbuf[tid] += rbuf[tid+s];
        __syncthreads();
    }
    float nrm = fmaxf(sqrtf(rbuf[0]), 1e-12f);
    if (tid < PD) out[g*PD + tid] = lg[tid] / nrm;
    out[BG*PD + g*HD + tid] = o[tid];
}

// ---------------- driver: single side stream (leak-safe envelope) --------
extern "C" void kernel_launch(void* const* d_in, const int* in_sizes, int n_in,
                              void* d_out, int out_size) {
    const int*   tokens = (const int*)  d_in[0];
    const int*   src    = (const int*)  d_in[1];
    const int*   dst    = (const int*)  d_in[2];
    const float* eattr  = (const float*)d_in[3];
    const float* emb    = (const float*)d_in[4];
    const float* W0     = (const float*)d_in[5];
    const float* b0     = (const float*)d_in[6];
    const float* W1     = (const float*)d_in[7];
    const float* b1     = (const float*)d_in[8];
    const float* p0     = (const float*)d_in[9];
    const float* p1     = (const float*)d_in[10];
    const float* wg     = (const float*)d_in[11];
    const float* bg     = (const float*)d_in[12];
    const float* Wp1    = (const float*)d_in[13];
    const float* bp1    = (const float*)d_in[14];
    const float* Wp2    = (const float*)d_in[15];
    const float* bp2    = (const float*)d_in[16];
    float* out = (float*)d_out;

    cudaFuncSetAttribute(gemm_mma_kernel,     cudaFuncAttributeMaxDynamicSharedMemorySize, GEMM_SMEM);
    cudaFuncSetAttribute(gemm2_gather_kernel, cudaFuncAttributeMaxDynamicSharedMemorySize, GEMM_SMEM);

    float* gh_dev = nullptr; cudaGetSymbolAddress((void**)&gh_dev, g_h);

    cudaStream_t s2;
    cudaStreamCreateWithFlags(&s2, cudaStreamNonBlocking);
    cudaEvent_t ev_fork, ev_w, ev_sa, ev_e1, ev_g1a, ev_t1, ev_e2;
    cudaEventCreateWithFlags(&ev_fork, cudaEventDisableTiming);
    cudaEventCreateWithFlags(&ev_w,    cudaEventDisableTiming);
    cudaEventCreateWithFlags(&ev_sa,   cudaEventDisableTiming);
    cudaEventCreateWithFlags(&ev_e1,   cudaEventDisableTiming);
    cudaEventCreateWithFlags(&ev_g1a,  cudaEventDisableTiming);
    cudaEventCreateWithFlags(&ev_t1,   cudaEventDisableTiming);
    cudaEventCreateWithFlags(&ev_e2,   cudaEventDisableTiming);

    cudaEventRecord(ev_fork, 0);
    cudaStreamWaitEvent(s2, ev_fork, 0);

    // s2: weights -> layer-1 edge pipeline -> gemm1a (after stA)
    wsplit_kernel<<<512, 256, 0, s2>>>(W0, W1);
    normp_kernel<<<2, HD, 0, s2>>>(p0, p1);
    cudaEventRecord(ev_w, s2);
    edge_build1_kernel<<<BG, 1024, 0, s2>>>(eattr, src, dst);
    cudaEventRecord(ev_e1, s2);

    // main: st halves; gemm1a overlaps half B on s2
    st_encode_kernel<<<NN/8, 256>>>(tokens, emb, 0);
    cudaEventRecord(ev_sa, 0);
    st_encode_kernel<<<NN/8, 256>>>(tokens, emb, NN/2);

    cudaStreamWaitEvent(s2, ev_sa, 0);
    gemm_mma_kernel<<<dim3(NN/256, 2), 256, GEMM_SMEM, s2>>>(0, 0, gh_dev);
    cudaEventRecord(ev_g1a, s2);

    cudaStreamWaitEvent(0, ev_w, 0);
    gemm_mma_kernel<<<dim3(NN/256, 2), 256, GEMM_SMEM>>>(0, NN/256, gh_dev);
    cudaStreamWaitEvent(0, ev_g1a, 0);
    cudaStreamWaitEvent(0, ev_e1, 0);
    gcn_agg_kernel<<<NN/4, 256>>>(b0, wg, 0);
    topk1_fused_kernel<<<BG, 512>>>(bg);
    cudaEventRecord(ev_t1, 0);

    // s2: layer-2 edge pipeline overlaps gemm2 on main
    cudaStreamWaitEvent(s2, ev_t1, 0);
    edge_build2_kernel<<<BG, 1024, 0, s2>>>(src, dst);
    cudaEventRecord(ev_e2, s2);

    // main: gemm2 with fused pool-gather, then agg2 + fused topk2/head
    gemm2_gather_kernel<<<dim3(N2/128, 2), 256, GEMM_SMEM>>>(gh_dev);
    cudaStreamWaitEvent(0, ev_e2, 0);
    gcn_agg_kernel<<<N2/4, 256>>>(b1, wg, 1);
    topk2_head_kernel<<<BG, 256>>>(bg, Wp1, bp1, Wp2, bp2, out);
}

// round 14
// speedup vs baseline: 1.0303x; 1.0239x over previous
#include <cuda_runtime.h>
#include <cuda_bf16.h>
#include <cstdint>

// ---------------- static problem config ----------------
#define BG   64
#define NPG  512
#define NN   (BG*NPG)     // 32768
#define EPG  8192
#define EE   (BG*EPG)     // 524288
#define LTOK 16
#define HD   256
#define PD   128
#define KP1  256
#define KP2  128
#define N2   (BG*KP1)     // 16384

// ---------------- device scratch ----------------
__device__ float g_w[EE];
__device__ float g_h[NN*HD];
__device__ float g_y[NN*HD];
__device__ __nv_bfloat16 g_xhi[NN*HD];
__device__ __nv_bfloat16 g_xlo[NN*HD];
__device__ float g_deg[NN];
__device__ float g_score[NN];
__device__ float g_ydw[NN];
__device__ float g_gatev[NN];
__device__ int   g_cnt[NN];
__device__ int   g_rowstart[NN];
__device__ int   g_csr[EE];
__device__ float g_csrw[EE];
__device__ int   g_nof[NN];
__device__ int   g_oldidx[NN];
__device__ float g_out[BG*HD];
__device__ float g_pn[2*HD];
__device__ __nv_bfloat16 g_WThi[2][HD*HD];
__device__ __nv_bfloat16 g_WTlo[2][HD*HD];

// ---------------- helpers ----------------
__device__ __forceinline__ uint32_t smem_u32(const void* p) {
    uint32_t a;
    asm("{ .reg .u64 t; cvta.to.shared.u64 t, %1; cvt.u32.u64 %0, t; }" : "=r"(a) : "l"(p));
    return a;
}
__device__ __forceinline__ void cp_async16(uint32_t dst, const void* src) {
    asm volatile("cp.async.ca.shared.global [%0], [%1], 16;" :: "r"(dst), "l"(src) : "memory");
}
#define CP_COMMIT() asm volatile("cp.async.commit_group;" ::: "memory")
#define CP_WAIT(n)  asm volatile("cp.async.wait_group %0;" :: "n"(n) : "memory")

__device__ __forceinline__ void split4(float4 v, uint2& hi, uint2& lo) {
    __nv_bfloat162 h0 = __floats2bfloat162_rn(v.x, v.y);
    __nv_bfloat162 h1 = __floats2bfloat162_rn(v.z, v.w);
    float rx = v.x - __bfloat162float(__low2bfloat16(h0));
    float ry = v.y - __bfloat162float(__high2bfloat16(h0));
    float rz = v.z - __bfloat162float(__low2bfloat16(h1));
    float rw = v.w - __bfloat162float(__high2bfloat16(h1));
    __nv_bfloat162 l0 = __floats2bfloat162_rn(rx, ry);
    __nv_bfloat162 l1 = __floats2bfloat162_rn(rz, rw);
    hi = make_uint2(*(uint32_t*)&h0, *(uint32_t*)&h1);
    lo = make_uint2(*(uint32_t*)&l0, *(uint32_t*)&l1);
}

// ---------------- ST encoder (node-range; fused nof=-1) -------------------
__global__ void __launch_bounds__(256) st_encode_kernel(const int* __restrict__ tokens,
                                                        const float* __restrict__ emb,
                                                        int node0) {
    int tid = threadIdx.x;
    int grp = tid >> 6, lane = tid & 63;
    int nbase = node0 + blockIdx.x * 4;
    int node = nbase + grp;
    __shared__ int toks[4*LTOK];
    if (tid < 4*LTOK) toks[tid] = tokens[nbase*LTOK + tid];
    if (lane == 0) g_nof[node] = -1;
    __syncthreads();
    const float4* emb4 = (const float4*)emb;
    float4 acc = {0.f, 0.f, 0.f, 0.f};
    int cnt = 0;
    #pragma unroll
    for (int l = 0; l < LTOK; l++) {
        int t = toks[grp*LTOK + l];
        if (t != 0) {
            float4 v = emb4[(size_t)t*64 + lane];
            acc.x += v.x; acc.y += v.y; acc.z += v.z; acc.w += v.w;
            cnt++;
        }
    }
    float inv = 1.f / (float)(cnt > 0 ? cnt : 1);
    acc.x *= inv; acc.y *= inv; acc.z *= inv; acc.w *= inv;
    size_t o = (size_t)node*64 + lane;
    uint2 hi, lo;
    split4(acc, hi, lo);
    ((uint2*)g_xhi)[o] = hi;
    ((uint2*)g_xlo)[o] = lo;
}

// ---------------- W^T bf16 split ----------------
__global__ void wsplit_kernel(const float* __restrict__ W0, const float* __restrict__ W1) {
    int b = blockIdx.x;
    int which = b >> 8, k = b & 255, n = threadIdx.x;
    const float* W = which ? W1 : W0;
    float v = W[k*HD + n];
    __nv_bfloat16 hi = __float2bfloat16(v);
    float lo = v - __bfloat162float(hi);
    g_WThi[which][n*HD + k] = hi;
    g_WTlo[which][n*HD + k] = __float2bfloat16(lo);
}

// ---------------- normalized p0,p1 ----------------
__global__ void normp_kernel(const float* __restrict__ p0, const float* __restrict__ p1) {
    __shared__ float red[HD];
    int which = blockIdx.x, tid = threadIdx.x;
    const float* p = which ? p1 : p0;
    float v = p[tid];
    red[tid] = v*v; __syncthreads();
    for (int s = HD/2; s > 0; s >>= 1) {
        if (tid < s) red[tid] += red[tid+s];
        __syncthreads();
    }
    g_pn[which*HD + tid] = v / sqrtf(red[0]);
}

// ======== fused edge pipeline, layer 1 =========
__global__ void __launch_bounds__(1024) edge_build1_kernel(const float* __restrict__ ea,
                                                           const int* __restrict__ src,
                                                           const int* __restrict__ dst) {
    __shared__ float sdeg[NPG];
    __shared__ int   scnt[NPG];
    __shared__ float sdinv[NPG];
    __shared__ int   scur[NPG];
    __shared__ int   sscan[NPG];
    int g = blockIdx.x, tid = threadIdx.x;
    int ebase = g * EPG;
    if (tid < NPG) { sdeg[tid] = 1.0f; scnt[tid] = 0; }
    __syncthreads();
    #pragma unroll
    for (int k = 0; k < EPG/1024; k++) {
        int e = ebase + k*1024 + tid;
        float w = 0.5f * (ea[2*e] + ea[2*e+1]);
        g_w[e] = w;
        int dl = dst[e] - g*NPG;
        atomicAdd(&sdeg[dl], w);
        atomicAdd(&scnt[dl], 1);
    }
    __syncthreads();
    int c = 0;
    if (tid < NPG) {
        int node = g*NPG + tid;
        float dg = sdeg[tid];
        c = scnt[tid];
        sdinv[tid] = rsqrtf(dg);
        g_deg[node] = dg;
        g_cnt[node] = c;
        sscan[tid] = c;
    }
    __syncthreads();
    for (int off = 1; off < NPG; off <<= 1) {
        int v = (tid >= off && tid < NPG) ? sscan[tid-off] : 0;
        __syncthreads();
        if (tid < NPG) sscan[tid] += v;
        __syncthreads();
    }
    if (tid < NPG) {
        int rs = ebase + sscan[tid] - c;
        g_rowstart[g*NPG + tid] = rs;
        scur[tid] = rs;
    }
    __syncthreads();
    #pragma unroll
    for (int k = 0; k < EPG/1024; k++) {
        int e = ebase + k*1024 + tid;
        int sl = src[e] - g*NPG;
        int dl = dst[e] - g*NPG;
        float w = g_w[e];
        int pos = atomicAdd(&scur[dl], 1);
        g_csr[pos]  = g*NPG + sl;
        g_csrw[pos] = sdinv[sl] * w * sdinv[dl];
    }
}

// ======== fused edge pipeline, layer 2 ======
__global__ void __launch_bounds__(1024) edge_build2_kernel(const int* __restrict__ src,
                                                           const int* __restrict__ dst) {
    __shared__ float sdeg[KP1];
    __shared__ int   scnt[KP1];
    __shared__ float sdinv[KP1];
    __shared__ int   scur[KP1];
    __shared__ int   sscan[KP1];
    int g = blockIdx.x, tid = threadIdx.x;
    int ebase = g * EPG;
    if (tid < KP1) { sdeg[tid] = 1.0f; scnt[tid] = 0; }
    __syncthreads();
    #pragma unroll
    for (int k = 0; k < EPG/1024; k++) {
        int e = ebase + k*1024 + tid;
        int ns = g_nof[src[e]], nd = g_nof[dst[e]];
        if (ns >= 0 && nd >= 0) {
            float w = g_w[e];
            int dl = nd - g*KP1;
            atomicAdd(&sdeg[dl], w);
            atomicAdd(&scnt[dl], 1);
        }
    }
    __syncthreads();
    int c = 0;
    if (tid < KP1) {
        int node = g*KP1 + tid;
        float dg = sdeg[tid];
        c = scnt[tid];
        sdinv[tid] = rsqrtf(dg);
        g_deg[node] = dg;
        g_cnt[node] = c;
        sscan[tid] = c;
    }
    __syncthreads();
    for (int off = 1; off < KP1; off <<= 1) {
        int v = (tid >= off && tid < KP1) ? sscan[tid-off] : 0;
        __syncthreads();
        if (tid < KP1) sscan[tid] += v;
        __syncthreads();
    }
    if (tid < KP1) {
        int rs = ebase + sscan[tid] - c;
        g_rowstart[g*KP1 + tid] = rs;
        scur[tid] = rs;
    }
    __syncthreads();
    #pragma unroll
    for (int k = 0; k < EPG/1024; k++) {
        int e = ebase + k*1024 + tid;
        int ns = g_nof[src[e]], nd = g_nof[dst[e]];
        if (ns >= 0 && nd >= 0) {
            float w = g_w[e];
            int sl = ns - g*KP1, dl = nd - g*KP1;
            int pos = atomicAdd(&scur[dl], 1);
            g_csr[pos]  = ns;
            g_csrw[pos] = sdinv[sl] * w * sdinv[dl];
        }
    }
}

// ================= GEMM common =================
#define ASTR 72
#define OFF_AH 0
#define OFF_AL (128*ASTR)
#define OFF_BH (2*128*ASTR)
#define OFF_BL (3*128*ASTR)
#define BUF_ELEMS (4*128*ASTR)
#define GEMM_SMEM (2*BUF_ELEMS*2)

__device__ __forceinline__ void mma_bf16(float* c, const uint32_t* a,
                                         uint32_t b0, uint32_t b1) {
    asm volatile(
        "mma.sync.aligned.m16n8k16.row.col.f32.bf16.bf16.f32 "
        "{%0,%1,%2,%3},{%4,%5,%6,%7},{%8,%9},{%0,%1,%2,%3};"
        : "+f"(c[0]), "+f"(c[1]), "+f"(c[2]), "+f"(c[3])
        : "r"(a[0]), "r"(a[1]), "r"(a[2]), "r"(a[3]), "r"(b0), "r"(b1));
}

__device__ __forceinline__ void gemm_compute_chunk(const __nv_bfloat16* buf,
                                                   float acc[2][8][4],
                                                   int wm, int wn, int gg, int tt) {
    #pragma unroll
    for (int ks = 0; ks < 4; ks++) {
        uint32_t ah[2][4], al[2][4];
        #pragma unroll
        for (int mt = 0; mt < 2; mt++) {
            int r0 = wm*32 + mt*16 + gg;
            const __nv_bfloat16* bh = buf + ks*16 + tt*2;
            ah[mt][0] = *(const uint32_t*)(bh + OFF_AH + r0*ASTR);
            ah[mt][1] = *(const uint32_t*)(bh + OFF_AH + (r0+8)*ASTR);
            ah[mt][2] = *(const uint32_t*)(bh + OFF_AH + r0*ASTR + 8);
            ah[mt][3] = *(const uint32_t*)(bh + OFF_AH + (r0+8)*ASTR + 8);
            al[mt][0] = *(const uint32_t*)(bh + OFF_AL + r0*ASTR);
            al[mt][1] = *(const uint32_t*)(bh + OFF_AL + (r0+8)*ASTR);
            al[mt][2] = *(const uint32_t*)(bh + OFF_AL + r0*ASTR + 8);
            al[mt][3] = *(const uint32_t*)(bh + OFF_AL + (r0+8)*ASTR + 8);
        }
        #pragma unroll
        for (int nt = 0; nt < 8; nt++) {
            int n0 = wn*64 + nt*8 + gg;
            const __nv_bfloat16* bb2 = buf + n0*ASTR + ks*16 + tt*2;
            uint32_t bh0 = *(const uint32_t*)(bb2 + OFF_BH);
            uint32_t bh1 = *(const uint32_t*)(bb2 + OFF_BH + 8);
            uint32_t bl0 = *(const uint32_t*)(bb2 + OFF_BL);
            uint32_t bl1 = *(const uint32_t*)(bb2 + OFF_BL + 8);
            #pragma unroll
            for (int mt = 0; mt < 2; mt++) {
                mma_bf16(acc[mt][nt], ah[mt], bh0, bh1);
                mma_bf16(acc[mt][nt], al[mt], bh0, bh1);
                mma_bf16(acc[mt][nt], ah[mt], bl0, bl1);
            }
        }
    }
}

__device__ __forceinline__ void gemm_epilogue(float acc[2][8][4], float* C,
                                              int bm, int bn, int wm, int wn,
                                              int gg, int tt) {
    #pragma unroll
    for (int mt = 0; mt < 2; mt++) {
        int row = bm*128 + wm*32 + mt*16 + gg;
        #pragma unroll
        for (int nt = 0; nt < 8; nt++) {
            int col = bn*128 + wn*64 + nt*8 + tt*2;
            float2 v0 = {acc[mt][nt][0], acc[mt][nt][1]};
            float2 v1 = {acc[mt][nt][2], acc[mt][nt][3]};
            *(float2*)(C + (size_t)row*HD + col)     = v0;
            *(float2*)(C + (size_t)(row+8)*HD + col) = v1;
        }
    }
}

// ---- layer-1 GEMM: A from pre-split xhi/xlo, fully cp.async ----
__global__ void __launch_bounds__(256, 1) gemm_mma_kernel(int which, int bm0,
                                                          float* __restrict__ C) {
    extern __shared__ __align__(16) __nv_bfloat16 sm[];
    int tid = threadIdx.x;
    int bm = bm0 + blockIdx.x, bn = blockIdx.y;
    int warp = tid >> 5, lane = tid & 31;
    int wm = warp >> 1, wn = warp & 1;
    int gg = lane >> 2, tt = lane & 3;

    const __nv_bfloat16* Ah = g_xhi + (size_t)(bm*128) * HD;
    const __nv_bfloat16* Al = g_xlo + (size_t)(bm*128) * HD;
    const __nv_bfloat16* Bh = g_WThi[which] + (size_t)(bn*128) * HD;
    const __nv_bfloat16* Bl = g_WTlo[which] + (size_t)(bn*128) * HD;
    uint32_t sbase = smem_u32(sm);

    float acc[2][8][4];
    #pragma unroll
    for (int mt = 0; mt < 2; mt++)
        #pragma unroll
        for (int nt = 0; nt < 8; nt++)
            #pragma unroll
            for (int q = 0; q < 4; q++) acc[mt][nt][q] = 0.f;

    auto issue = [&](int kc, int buf) {
        uint32_t bb = sbase + buf * (BUF_ELEMS*2);
        #pragma unroll
        for (int it = 0; it < 4; it++) {
            int u = it*256 + tid;
            int row = u >> 3, seg = u & 7;
            size_t go = (size_t)row*HD + kc*64 + seg*8;
            uint32_t so = (row*ASTR + seg*8) * 2;
            cp_async16(bb + OFF_AH*2 + so, Ah + go);
            cp_async16(bb + OFF_AL*2 + so, Al + go);
            cp_async16(bb + OFF_BH*2 + so, Bh + go);
            cp_async16(bb + OFF_BL*2 + so, Bl + go);
        }
        CP_COMMIT();
    };

    issue(0, 0);
    #pragma unroll
    for (int kc = 0; kc < 4; kc++) {
        if (kc < 3) { issue(kc+1, (kc+1)&1); CP_WAIT(1); }
        else        { CP_WAIT(0); }
        __syncthreads();
        gemm_compute_chunk(sm + (kc&1)*BUF_ELEMS, acc, wm, wn, gg, tt);
        __syncthreads();
    }
    gemm_epilogue(acc, C, bm, bn, wm, wn, gg, tt);
}

// ---- layer-2 GEMM: A gathered from g_y via oldidx/gatev, split on the fly --
__global__ void __launch_bounds__(256, 1) gemm2_gather_kernel(float* __restrict__ C) {
    extern __shared__ __align__(16) __nv_bfloat16 sm[];
    int tid = threadIdx.x;
    int bm = blockIdx.x, bn = blockIdx.y;
    int warp = tid >> 5, lane = tid & 31;
    int wm = warp >> 1, wn = warp & 1;
    int gg = lane >> 2, tt = lane & 3;

    const __nv_bfloat16* Bh = g_WThi[1] + (size_t)(bn*128) * HD;
    const __nv_bfloat16* Bl = g_WTlo[1] + (size_t)(bn*128) * HD;
    uint32_t sbase = smem_u32(sm);

    float acc[2][8][4];
    #pragma unroll
    for (int mt = 0; mt < 2; mt++)
        #pragma unroll
        for (int nt = 0; nt < 8; nt++)
            #pragma unroll
            for (int q = 0; q < 4; q++) acc[mt][nt][q] = 0.f;

    auto issueB = [&](int kc, int buf) {
        uint32_t bb = sbase + buf * (BUF_ELEMS*2);
        #pragma unroll
        for (int it = 0; it < 4; it++) {
            int u = it*256 + tid;
            int row = u >> 3, seg = u & 7;
            size_t go = (size_t)row*HD + kc*64 + seg*8;
            uint32_t so = (row*ASTR + seg*8) * 2;
            cp_async16(bb + OFF_BH*2 + so, Bh + go);
            cp_async16(bb + OFF_BL*2 + so, Bl + go);
        }
        CP_COMMIT();
    };
    auto stageA = [&](int kc, int buf) {
        __nv_bfloat16* dst = sm + buf * BUF_ELEMS;
        #pragma unroll
        for (int it = 0; it < 4; it++) {
            int u = it*256 + tid;
            int row = u >> 3, seg = u & 7;
            int nid = bm*128 + row;
            int old = g_oldidx[nid];
            float gv = g_gatev[nid];
            const float4* yp = (const float4*)(g_y + (size_t)old*HD + kc*64 + seg*8);
            float4 v0 = yp[0], v1 = yp[1];
            v0.x *= gv; v0.y *= gv; v0.z *= gv; v0.w *= gv;
            v1.x *= gv; v1.y *= gv; v1.z *= gv; v1.w *= gv;
            uint2 h0, l0, h1, l1;
            split4(v0, h0, l0);
            split4(v1, h1, l1);
            int so = row*ASTR + seg*8;
            *(uint2*)(dst + OFF_AH + so)     = h0;
            *(uint2*)(dst + OFF_AH + so + 4) = h1;
            *(uint2*)(dst + OFF_AL + so)     = l0;
            *(uint2*)(dst + OFF_AL + so + 4) = l1;
        }
    };

    issueB(0, 0);
    stageA(0, 0);
    #pragma unroll
    for (int kc = 0; kc < 4; kc++) {
        if (kc < 3) {
            issueB(kc+1, (kc+1)&1);
            stageA(kc+1, (kc+1)&1);
            CP_WAIT(1);
        } else {
            CP_WAIT(0);
        }
        __syncthreads();
        gemm_compute_chunk(sm + (kc&1)*BUF_ELEMS, acc, wm, wn, gg, tt);
        __syncthreads();
    }
    gemm_epilogue(acc, C, bm, bn, wm, wn, gg, tt);
}

// ---------------- GCN aggregate + relu (node range; fused dots) -----------
__global__ void __launch_bounds__(256) gcn_agg_kernel(const float* __restrict__ b,
                                                      const float* __restrict__ wg,
                                                      int which, int node0) {
    __shared__ float sred[8];
    __shared__ float sred2[8];
    int tid = threadIdx.x;
    int grp = tid >> 6, lane = tid & 63, wid = tid >> 5;
    int i = node0 + blockIdx.x * 4 + grp;
    int rs = g_rowstart[i], c = g_cnt[i];
    const float4* h4 = (const float4*)g_h;
    float4 acc = {0.f, 0.f, 0.f, 0.f};
    int j = 0;
    for (; j + 4 <= c; j += 4) {
        int   s0 = g_csr[rs+j],   s1 = g_csr[rs+j+1],  s2 = g_csr[rs+j+2],  s3 = g_csr[rs+j+3];
        float w0 = g_csrw[rs+j],  w1 = g_csrw[rs+j+1], w2 = g_csrw[rs+j+2], w3 = g_csrw[rs+j+3];
        float4 x0 = h4[(size_t)s0*64 + lane];
        float4 x1 = h4[(size_t)s1*64 + lane];
        float4 x2 = h4[(size_t)s2*64 + lane];
        float4 x3 = h4[(size_t)s3*64 + lane];
        acc.x = fmaf(x0.x, w0, acc.x); acc.y = fmaf(x0.y, w0, acc.y);
        acc.z = fmaf(x0.z, w0, acc.z); acc.w = fmaf(x0.w, w0, acc.w);
        acc.x = fmaf(x1.x, w1, acc.x); acc.y = fmaf(x1.y, w1, acc.y);
        acc.z = fmaf(x1.z, w1, acc.z); acc.w = fmaf(x1.w, w1, acc.w);
        acc.x = fmaf(x2.x, w2, acc.x); acc.y = fmaf(x2.y, w2, acc.y);
        acc.z = fmaf(x2.z, w2, acc.z); acc.w = fmaf(x2.w, w2, acc.w);
        acc.x = fmaf(x3.x, w3, acc.x); acc.y = fmaf(x3.y, w3, acc.y);
        acc.z = fmaf(x3.z, w3, acc.z); acc.w = fmaf(x3.w, w3, acc.w);
    }
    for (; j < c; j++) {
        int   s0 = g_csr[rs+j];
        float w0 = g_csrw[rs+j];
        float4 x0 = h4[(size_t)s0*64 + lane];
        acc.x = fmaf(x0.x, w0, acc.x); acc.y = fmaf(x0.y, w0, acc.y);
        acc.z = fmaf(x0.z, w0, acc.z); acc.w = fmaf(x0.w, w0, acc.w);
    }
    float sl = 1.0f / g_deg[i];
    float4 xi = h4[(size_t)i*64 + lane];
    float4 bb = ((const float4*)b)[lane];
    float4 v;
    v.x = fmaxf(fmaf(xi.x, sl, acc.x) + bb.x, 0.f);
    v.y = fmaxf(fmaf(xi.y, sl, acc.y) + bb.y, 0.f);
    v.z = fmaxf(fmaf(xi.z, sl, acc.z) + bb.z, 0.f);
    v.w = fmaxf(fmaf(xi.w, sl, acc.w) + bb.w, 0.f);
    ((float4*)g_y)[(size_t)i*64 + lane] = v;
    float4 pn = ((const float4*)(g_pn + which*HD))[lane];
    float4 wg4 = ((const float4*)wg)[lane];
    float s  = v.x*pn.x + v.y*pn.y + v.z*pn.z + v.w*pn.w;
    float s2 = v.x*wg4.x + v.y*wg4.y + v.z*wg4.z + v.w*wg4.w;
    #pragma unroll
    for (int o = 16; o > 0; o >>= 1) {
        s  += __shfl_down_sync(0xffffffffu, s,  o);
        s2 += __shfl_down_sync(0xffffffffu, s2, o);
    }
    if ((tid & 31) == 0) { sred[wid] = s; sred2[wid] = s2; }
    __syncthreads();
    if (tid < 4) {
        int i2 = node0 + blockIdx.x*4 + tid;
        g_score[i2] = sred[2*tid]  + sred[2*tid+1];
        g_ydw[i2]   = sred2[2*tid] + sred2[2*tid+1];
    }
}

// -------- layer-1 fused top-k + gates + softmax + attention pool ----------
__global__ void topk1_fused_kernel(const float* __restrict__ bg) {
    __shared__ float sv[512];
    __shared__ int   si[512];
    __shared__ int   sold[256];
    __shared__ float scoef[256];
    __shared__ float rbuf[512];
    const int n_per = NPG, k = KP1;
    int g = blockIdx.x, tid = threadIdx.x;
    sv[tid] = g_score[g*n_per + tid];
    si[tid] = tid;
    __syncthreads();
    for (int ksz = 2; ksz <= n_per; ksz <<= 1) {
        for (int j = ksz >> 1; j > 0; j >>= 1) {
            int ixj = tid ^ j;
            if (ixj > tid) {
                bool asc = ((tid & ksz) == 0);
                float v1 = sv[tid], v2 = sv[ixj];
                int   i1 = si[tid], i2 = si[ixj];
                bool b12 = (v1 > v2) || (v1 == v2 && i1 < i2);
                if (asc != b12) {
                    sv[tid] = v2; si[tid] = i2;
                    sv[ixj] = v1; si[ixj] = i1;
                }
            }
            __syncthreads();
        }
    }
    float tanhv = 0.f, gate = -1e30f;
    int old = 0;
    if (tid < k) {
        old = g*n_per + si[tid];
        tanhv = tanhf(sv[tid]);
        int nid = g*k + tid;
        g_nof[old]    = nid;
        g_oldidx[nid] = old;
        g_gatev[nid]  = tanhv;
        sold[tid] = old;
        gate = tanhv * g_ydw[old] + bg[0];
    }
    __syncthreads();
    rbuf[tid] = gate;
    __syncthreads();
    for (int s = 256; s > 0; s >>= 1) {
        if (tid < s) rbuf[tid] = fmaxf(rbuf[tid], rbuf[tid+s]);
        __syncthreads();
    }
    float mx = rbuf[0];
    __syncthreads();
    float e = (tid < k) ? expf(gate - mx) : 0.f;
    rbuf[tid] = e;
    __syncthreads();
    for (int s = 256; s > 0; s >>= 1) {
        if (tid < s) rbuf[tid] += rbuf[tid+s];
        __syncthreads();
    }
    float inv = 1.f / rbuf[0];
    if (tid < k) scoef[tid] = e * inv * tanhv;
    __syncthreads();
    int f = tid & 255;
    int i0 = (tid < 256) ? 0 : k/2;
    int i1 = (tid < 256) ? k/2 : k;
    float acc = 0.f;
    for (int i = i0; i < i1; i++)
        acc = fmaf(scoef[i], g_y[(size_t)sold[i]*HD + f], acc);
    rbuf[tid] = acc;
    __syncthreads();
    if (tid < 256) g_out[g*HD + f] = rbuf[tid] + rbuf[tid+256];
}

// -------- layer-2 fused top-k + attention pool + projection head ----------
__global__ void topk2_head_kernel(const float* __restrict__ bg,
                                  const float* __restrict__ Wp1,
                                  const float* __restrict__ bp1,
                                  const float* __restrict__ Wp2,
                                  const float* __restrict__ bp2,
                                  float* __restrict__ out) {
    __shared__ float sv[256];
    __shared__ int   si[256];
    __shared__ int   sold[128];
    __shared__ float scoef[128];
    __shared__ float rbuf[256];
    __shared__ float o[HD];
    __shared__ float hs[PD];
    __shared__ float lg[PD];
    const int n_per = KP1, k = KP2;
    int g = blockIdx.x, tid = threadIdx.x;
    sv[tid] = g_score[g*n_per + tid];
    si[tid] = tid;
    __syncthreads();
    for (int ksz = 2; ksz <= n_per; ksz <<= 1) {
        for (int j = ksz >> 1; j > 0; j >>= 1) {
            int ixj = tid ^ j;
            if (ixj > tid) {
                bool asc = ((tid & ksz) == 0);
                float v1 = sv[tid], v2 = sv[ixj];
                int   i1 = si[tid], i2 = si[ixj];
                bool b12 = (v1 > v2) || (v1 == v2 && i1 < i2);
                if (asc != b12) {
                    sv[tid] = v2; si[tid] = i2;
                    sv[ixj] = v1; si[ixj] = i1;
                }
            }
            __syncthreads();
        }
    }
    float tanhv = 0.f, gate = -1e30f;
    int old = 0;
    if (tid < k) {
        old = g*n_per + si[tid];
        tanhv = tanhf(sv[tid]);
        sold[tid] = old;
        gate = tanhv * g_ydw[old] + bg[0];
    }
    __syncthreads();
    rbuf[tid] = gate;
    __syncthreads();
    for (int s = 128; s > 0; s >>= 1) {
        if (tid < s) rbuf[tid] = fmaxf(rbuf[tid], rbuf[tid+s]);
        __syncthreads();
    }
    float mx = rbuf[0];
    __syncthreads();
    float e = (tid < k) ? expf(gate - mx) : 0.f;
    rbuf[tid] = e;
    __syncthreads();
    for (int s = 128; s > 0; s >>= 1) {
        if (tid < s) rbuf[tid] += rbuf[tid+s];
        __syncthreads();
    }
    float inv = 1.f / rbuf[0];
    if (tid < k) scoef[tid] = e * inv * tanhv;
    __syncthreads();
    float acc = 0.f;
    for (int i = 0; i < k; i++)
        acc = fmaf(scoef[i], g_y[(size_t)sold[i]*HD + tid], acc);
    o[tid] = g_out[g*HD + tid] + acc;
    __syncthreads();
    if (tid < PD) {
        float s = bp1[tid];
        for (int kk = 0; kk < HD; kk++) s = fmaf(o[kk], Wp1[kk*PD + tid], s);
        hs[tid] = fmaxf(s, 0.f);
    }
    __syncthreads();
    if (tid < PD) {
        float s = bp2[tid];
        for (int kk = 0; kk < PD; kk++) s = fmaf(hs[kk], Wp2[kk*PD + tid], s);
        lg[tid] = s;
        rbuf[tid] = s * s;
    }
    __syncthreads();
    for (int s = 64; s > 0; s >>= 1) {
        if (tid < s) rbuf[tid] += rbuf[tid+s];
        __syncthreads();
    }
    float nrm = fmaxf(sqrtf(rbuf[0]), 1e-12f);
    if (tid < PD) out[g*PD + tid] = lg[tid] / nrm;
    out[BG*PD + g*HD + tid] = o[tid];
}

// ---------------- driver: staged-offset overlap, 1 side stream -----------
extern "C" void kernel_launch(void* const* d_in, const int* in_sizes, int n_in,
                              void* d_out, int out_size) {
    const int*   tokens = (const int*)  d_in[0];
    const int*   src    = (const int*)  d_in[1];
    const int*   dst    = (const int*)  d_in[2];
    const float* eattr  = (const float*)d_in[3];
    const float* emb    = (const float*)d_in[4];
    const float* W0     = (const float*)d_in[5];
    const float* b0     = (const float*)d_in[6];
    const float* W1     = (const float*)d_in[7];
    const float* b1     = (const float*)d_in[8];
    const float* p0     = (const float*)d_in[9];
    const float* p1     = (const float*)d_in[10];
    const float* wg     = (const float*)d_in[11];
    const float* bg     = (const float*)d_in[12];
    const float* Wp1    = (const float*)d_in[13];
    const float* bp1    = (const float*)d_in[14];
    const float* Wp2    = (const float*)d_in[15];
    const float* bp2    = (const float*)d_in[16];
    float* out = (float*)d_out;

    cudaFuncSetAttribute(gemm_mma_kernel,     cudaFuncAttributeMaxDynamicSharedMemorySize, GEMM_SMEM);
    cudaFuncSetAttribute(gemm2_gather_kernel, cudaFuncAttributeMaxDynamicSharedMemorySize, GEMM_SMEM);

    float* gh_dev = nullptr; cudaGetSymbolAddress((void**)&gh_dev, g_h);

    cudaStream_t s2;
    cudaStreamCreateWithFlags(&s2, cudaStreamNonBlocking);
    cudaEvent_t ev_fork, ev_w, ev_sa, ev_e1, ev_a1a, ev_t1, ev_e2;
    cudaEventCreateWithFlags(&ev_fork, cudaEventDisableTiming);
    cudaEventCreateWithFlags(&ev_w,    cudaEventDisableTiming);
    cudaEventCreateWithFlags(&ev_sa,   cudaEventDisableTiming);
    cudaEventCreateWithFlags(&ev_e1,   cudaEventDisableTiming);
    cudaEventCreateWithFlags(&ev_a1a,  cudaEventDisableTiming);
    cudaEventCreateWithFlags(&ev_t1,   cudaEventDisableTiming);
    cudaEventCreateWithFlags(&ev_e2,   cudaEventDisableTiming);

    cudaEventRecord(ev_fork, 0);
    cudaStreamWaitEvent(s2, ev_fork, 0);

    // s2: weights -> edge pipeline 1 -> gemm1a -> agg1a (half A, staged)
    wsplit_kernel<<<512, 256, 0, s2>>>(W0, W1);
    normp_kernel<<<2, HD, 0, s2>>>(p0, p1);
    cudaEventRecord(ev_w, s2);
    edge_build1_kernel<<<BG, 1024, 0, s2>>>(eattr, src, dst);
    cudaEventRecord(ev_e1, s2);

    // main: st halves
    st_encode_kernel<<<NN/8, 256>>>(tokens, emb, 0);
    cudaEventRecord(ev_sa, 0);
    st_encode_kernel<<<NN/8, 256>>>(tokens, emb, NN/2);

    // s2: gemm1a (rows 0..NN/2) then agg1a (graphs 0..31)
    cudaStreamWaitEvent(s2, ev_sa, 0);
    gemm_mma_kernel<<<dim3(NN/256, 2), 256, GEMM_SMEM, s2>>>(0, 0, gh_dev);
    gcn_agg_kernel<<<NN/8, 256, 0, s2>>>(b0, wg, 0, 0);
    cudaEventRecord(ev_a1a, s2);

    // main: gemm1b -> agg1b (overlaps agg1a on s2)
    cudaStreamWaitEvent(0, ev_w, 0);
    gemm_mma_kernel<<<dim3(NN/256, 2), 256, GEMM_SMEM>>>(0, NN/256, gh_dev);
    cudaStreamWaitEvent(0, ev_e1, 0);
    gcn_agg_kernel<<<NN/8, 256>>>(b0, wg, 0, NN/2);
    cudaStreamWaitEvent(0, ev_a1a, 0);
    topk1_fused_kernel<<<BG, 512>>>(bg);
    cudaEventRecord(ev_t1, 0);

    // s2: layer-2 edge pipeline overlaps gemm2 on main
    cudaStreamWaitEvent(s2, ev_t1, 0);
    edge_build2_kernel<<<BG, 1024, 0, s2>>>(src, dst);
    cudaEventRecord(ev_e2, s2);

    // main: gemm2 (fused pool-gather) -> agg2 -> topk2+head
    gemm2_gather_kernel<<<dim3(N2/128, 2), 256, GEMM_SMEM>>>(gh_dev);
    cudaStreamWaitEvent(0, ev_e2, 0);
    gcn_agg_kernel<<<N2/4, 256>>>(b1, wg, 1, 0);
    topk2_head_kernel<<<BG, 256>>>(bg, Wp1, bp1, Wp2, bp2, out);
}

// round 15
// speedup vs baseline: 1.0568x; 1.0257x over previous
#include <cuda_runtime.h>
#include <cuda_bf16.h>
#include <cstdint>

// ---------------- static problem config ----------------
#define BG   64
#define NPG  512
#define NN   (BG*NPG)     // 32768
#define EPG  8192
#define EE   (BG*EPG)     // 524288
#define LTOK 16
#define HD   256
#define PD   128
#define KP1  256
#define KP2  128
#define N2   (BG*KP1)     // 16384

// ---------------- device scratch ----------------
__device__ float g_w[EE];
__device__ float g_h[NN*HD];
__device__ float g_y[NN*HD];
__device__ __nv_bfloat16 g_xhi[NN*HD];
__device__ __nv_bfloat16 g_xlo[NN*HD];
__device__ float g_deg[NN];
__device__ float g_score[NN];
__device__ float g_ydw[NN];
__device__ float g_gatev[NN];
__device__ int   g_cnt[NN];
__device__ int   g_rowstart[NN];
__device__ int   g_csr[EE];
__device__ float g_csrw[EE];
__device__ int   g_nof[NN];
__device__ int   g_oldidx[NN];
__device__ float g_out[BG*HD];
__device__ float g_pn[2*HD];
__device__ __nv_bfloat16 g_WThi[2][HD*HD];
__device__ __nv_bfloat16 g_WTlo[2][HD*HD];

// ---------------- helpers ----------------
__device__ __forceinline__ uint32_t smem_u32(const void* p) {
    uint32_t a;
    asm("{ .reg .u64 t; cvta.to.shared.u64 t, %1; cvt.u32.u64 %0, t; }" : "=r"(a) : "l"(p));
    return a;
}
__device__ __forceinline__ void cp_async16(uint32_t dst, const void* src) {
    asm volatile("cp.async.ca.shared.global [%0], [%1], 16;" :: "r"(dst), "l"(src) : "memory");
}
#define CP_COMMIT() asm volatile("cp.async.commit_group;" ::: "memory")
#define CP_WAIT(n)  asm volatile("cp.async.wait_group %0;" :: "n"(n) : "memory")

__device__ __forceinline__ void split4(float4 v, uint2& hi, uint2& lo) {
    __nv_bfloat162 h0 = __floats2bfloat162_rn(v.x, v.y);
    __nv_bfloat162 h1 = __floats2bfloat162_rn(v.z, v.w);
    float rx = v.x - __bfloat162float(__low2bfloat16(h0));
    float ry = v.y - __bfloat162float(__high2bfloat16(h0));
    float rz = v.z - __bfloat162float(__low2bfloat16(h1));
    float rw = v.w - __bfloat162float(__high2bfloat16(h1));
    __nv_bfloat162 l0 = __floats2bfloat162_rn(rx, ry);
    __nv_bfloat162 l1 = __floats2bfloat162_rn(rz, rw);
    hi = make_uint2(*(uint32_t*)&h0, *(uint32_t*)&h1);
    lo = make_uint2(*(uint32_t*)&l0, *(uint32_t*)&l1);
}

// ---------------- ST encoder: 2 acc chains + occupancy bound --------------
__global__ void __launch_bounds__(256, 6) st_encode_kernel(const int* __restrict__ tokens,
                                                           const float* __restrict__ emb,
                                                           int node0) {
    int tid = threadIdx.x;
    int grp = tid >> 6, lane = tid & 63;
    int nbase = node0 + blockIdx.x * 4;
    int node = nbase + grp;
    __shared__ int toks[4*LTOK];
    if (tid < 4*LTOK) toks[tid] = tokens[nbase*LTOK + tid];
    if (lane == 0) g_nof[node] = -1;
    __syncthreads();
    const float4* emb4 = (const float4*)emb;
    float4 a0 = {0.f, 0.f, 0.f, 0.f};
    float4 a1 = {0.f, 0.f, 0.f, 0.f};
    int cnt = 0;
    #pragma unroll
    for (int l = 0; l < LTOK; l += 2) {
        int t0 = toks[grp*LTOK + l];
        int t1 = toks[grp*LTOK + l + 1];
        if (t0 != 0) {
            float4 v = emb4[(size_t)t0*64 + lane];
            a0.x += v.x; a0.y += v.y; a0.z += v.z; a0.w += v.w;
            cnt++;
        }
        if (t1 != 0) {
            float4 v = emb4[(size_t)t1*64 + lane];
            a1.x += v.x; a1.y += v.y; a1.z += v.z; a1.w += v.w;
            cnt++;
        }
    }
    float inv = 1.f / (float)(cnt > 0 ? cnt : 1);
    float4 acc;
    acc.x = (a0.x + a1.x) * inv;
    acc.y = (a0.y + a1.y) * inv;
    acc.z = (a0.z + a1.z) * inv;
    acc.w = (a0.w + a1.w) * inv;
    size_t o = (size_t)node*64 + lane;
    uint2 hi, lo;
    split4(acc, hi, lo);
    ((uint2*)g_xhi)[o] = hi;
    ((uint2*)g_xlo)[o] = lo;
}

// ---------------- W^T bf16 split ----------------
__global__ void wsplit_kernel(const float* __restrict__ W0, const float* __restrict__ W1) {
    int b = blockIdx.x;
    int which = b >> 8, k = b & 255, n = threadIdx.x;
    const float* W = which ? W1 : W0;
    float v = W[k*HD + n];
    __nv_bfloat16 hi = __float2bfloat16(v);
    float lo = v - __bfloat162float(hi);
    g_WThi[which][n*HD + k] = hi;
    g_WTlo[which][n*HD + k] = __float2bfloat16(lo);
}

// ---------------- normalized p0,p1 ----------------
__global__ void normp_kernel(const float* __restrict__ p0, const float* __restrict__ p1) {
    __shared__ float red[HD];
    int which = blockIdx.x, tid = threadIdx.x;
    const float* p = which ? p1 : p0;
    float v = p[tid];
    red[tid] = v*v; __syncthreads();
    for (int s = HD/2; s > 0; s >>= 1) {
        if (tid < s) red[tid] += red[tid+s];
        __syncthreads();
    }
    g_pn[which*HD + tid] = v / sqrtf(red[0]);
}

// ======== fused edge pipeline, layer 1 =========
__global__ void __launch_bounds__(1024) edge_build1_kernel(const float* __restrict__ ea,
                                                           const int* __restrict__ src,
                                                           const int* __restrict__ dst) {
    __shared__ float sdeg[NPG];
    __shared__ int   scnt[NPG];
    __shared__ float sdinv[NPG];
    __shared__ int   scur[NPG];
    __shared__ int   sscan[NPG];
    int g = blockIdx.x, tid = threadIdx.x;
    int ebase = g * EPG;
    if (tid < NPG) { sdeg[tid] = 1.0f; scnt[tid] = 0; }
    __syncthreads();
    #pragma unroll
    for (int k = 0; k < EPG/1024; k++) {
        int e = ebase + k*1024 + tid;
        float w = 0.5f * (ea[2*e] + ea[2*e+1]);
        g_w[e] = w;
        int dl = dst[e] - g*NPG;
        atomicAdd(&sdeg[dl], w);
        atomicAdd(&scnt[dl], 1);
    }
    __syncthreads();
    int c = 0;
    if (tid < NPG) {
        int node = g*NPG + tid;
        float dg = sdeg[tid];
        c = scnt[tid];
        sdinv[tid] = rsqrtf(dg);
        g_deg[node] = dg;
        g_cnt[node] = c;
        sscan[tid] = c;
    }
    __syncthreads();
    for (int off = 1; off < NPG; off <<= 1) {
        int v = (tid >= off && tid < NPG) ? sscan[tid-off] : 0;
        __syncthreads();
        if (tid < NPG) sscan[tid] += v;
        __syncthreads();
    }
    if (tid < NPG) {
        int rs = ebase + sscan[tid] - c;
        g_rowstart[g*NPG + tid] = rs;
        scur[tid] = rs;
    }
    __syncthreads();
    #pragma unroll
    for (int k = 0; k < EPG/1024; k++) {
        int e = ebase + k*1024 + tid;
        int sl = src[e] - g*NPG;
        int dl = dst[e] - g*NPG;
        float w = g_w[e];
        int pos = atomicAdd(&scur[dl], 1);
        g_csr[pos]  = g*NPG + sl;
        g_csrw[pos] = sdinv[sl] * w * sdinv[dl];
    }
}

// ======== fused edge pipeline, layer 2 ======
__global__ void __launch_bounds__(1024) edge_build2_kernel(const int* __restrict__ src,
                                                           const int* __restrict__ dst) {
    __shared__ float sdeg[KP1];
    __shared__ int   scnt[KP1];
    __shared__ float sdinv[KP1];
    __shared__ int   scur[KP1];
    __shared__ int   sscan[KP1];
    int g = blockIdx.x, tid = threadIdx.x;
    int ebase = g * EPG;
    if (tid < KP1) { sdeg[tid] = 1.0f; scnt[tid] = 0; }
    __syncthreads();
    #pragma unroll
    for (int k = 0; k < EPG/1024; k++) {
        int e = ebase + k*1024 + tid;
        int ns = g_nof[src[e]], nd = g_nof[dst[e]];
        if (ns >= 0 && nd >= 0) {
            float w = g_w[e];
            int dl = nd - g*KP1;
            atomicAdd(&sdeg[dl], w);
            atomicAdd(&scnt[dl], 1);
        }
    }
    __syncthreads();
    int c = 0;
    if (tid < KP1) {
        int node = g*KP1 + tid;
        float dg = sdeg[tid];
        c = scnt[tid];
        sdinv[tid] = rsqrtf(dg);
        g_deg[node] = dg;
        g_cnt[node] = c;
        sscan[tid] = c;
    }
    __syncthreads();
    for (int off = 1; off < KP1; off <<= 1) {
        int v = (tid >= off && tid < KP1) ? sscan[tid-off] : 0;
        __syncthreads();
        if (tid < KP1) sscan[tid] += v;
        __syncthreads();
    }
    if (tid < KP1) {
        int rs = ebase + sscan[tid] - c;
        g_rowstart[g*KP1 + tid] = rs;
        scur[tid] = rs;
    }
    __syncthreads();
    #pragma unroll
    for (int k = 0; k < EPG/1024; k++) {
        int e = ebase + k*1024 + tid;
        int ns = g_nof[src[e]], nd = g_nof[dst[e]];
        if (ns >= 0 && nd >= 0) {
            float w = g_w[e];
            int sl = ns - g*KP1, dl = nd - g*KP1;
            int pos = atomicAdd(&scur[dl], 1);
            g_csr[pos]  = ns;
            g_csrw[pos] = sdinv[sl] * w * sdinv[dl];
        }
    }
}

// ================= GEMM common =================
#define ASTR 72
#define OFF_AH 0
#define OFF_AL (128*ASTR)
#define OFF_BH (2*128*ASTR)
#define OFF_BL (3*128*ASTR)
#define BUF_ELEMS (4*128*ASTR)
#define GEMM_SMEM (2*BUF_ELEMS*2)

__device__ __forceinline__ void mma_bf16(float* c, const uint32_t* a,
                                         uint32_t b0, uint32_t b1) {
    asm volatile(
        "mma.sync.aligned.m16n8k16.row.col.f32.bf16.bf16.f32 "
        "{%0,%1,%2,%3},{%4,%5,%6,%7},{%8,%9},{%0,%1,%2,%3};"
        : "+f"(c[0]), "+f"(c[1]), "+f"(c[2]), "+f"(c[3])
        : "r"(a[0]), "r"(a[1]), "r"(a[2]), "r"(a[3]), "r"(b0), "r"(b1));
}

__device__ __forceinline__ void gemm_compute_chunk(const __nv_bfloat16* buf,
                                                   float acc[2][8][4],
                                                   int wm, int wn, int gg, int tt) {
    #pragma unroll
    for (int ks = 0; ks < 4; ks++) {
        uint32_t ah[2][4], al[2][4];
        #pragma unroll
        for (int mt = 0; mt < 2; mt++) {
            int r0 = wm*32 + mt*16 + gg;
            const __nv_bfloat16* bh = buf + ks*16 + tt*2;
            ah[mt][0] = *(const uint32_t*)(bh + OFF_AH + r0*ASTR);
            ah[mt][1] = *(const uint32_t*)(bh + OFF_AH + (r0+8)*ASTR);
            ah[mt][2] = *(const uint32_t*)(bh + OFF_AH + r0*ASTR + 8);
            ah[mt][3] = *(const uint32_t*)(bh + OFF_AH + (r0+8)*ASTR + 8);
            al[mt][0] = *(const uint32_t*)(bh + OFF_AL + r0*ASTR);
            al[mt][1] = *(const uint32_t*)(bh + OFF_AL + (r0+8)*ASTR);
            al[mt][2] = *(const uint32_t*)(bh + OFF_AL + r0*ASTR + 8);
            al[mt][3] = *(const uint32_t*)(bh + OFF_AL + (r0+8)*ASTR + 8);
        }
        #pragma unroll
        for (int nt = 0; nt < 8; nt++) {
            int n0 = wn*64 + nt*8 + gg;
            const __nv_bfloat16* bb2 = buf + n0*ASTR + ks*16 + tt*2;
            uint32_t bh0 = *(const uint32_t*)(bb2 + OFF_BH);
            uint32_t bh1 = *(const uint32_t*)(bb2 + OFF_BH + 8);
            uint32_t bl0 = *(const uint32_t*)(bb2 + OFF_BL);
            uint32_t bl1 = *(const uint32_t*)(bb2 + OFF_BL + 8);
            #pragma unroll
            for (int mt = 0; mt < 2; mt++) {
                mma_bf16(acc[mt][nt], ah[mt], bh0, bh1);
                mma_bf16(acc[mt][nt], al[mt], bh0, bh1);
                mma_bf16(acc[mt][nt], ah[mt], bl0, bl1);
            }
        }
    }
}

__device__ __forceinline__ void gemm_epilogue(float acc[2][8][4], float* C,
                                              int bm, int bn, int wm, int wn,
                                              int gg, int tt) {
    #pragma unroll
    for (int mt = 0; mt < 2; mt++) {
        int row = bm*128 + wm*32 + mt*16 + gg;
        #pragma unroll
        for (int nt = 0; nt < 8; nt++) {
            int col = bn*128 + wn*64 + nt*8 + tt*2;
            float2 v0 = {acc[mt][nt][0], acc[mt][nt][1]};
            float2 v1 = {acc[mt][nt][2], acc[mt][nt][3]};
            *(float2*)(C + (size_t)row*HD + col)     = v0;
            *(float2*)(C + (size_t)(row+8)*HD + col) = v1;
        }
    }
}

// ---- layer-1 GEMM: A from pre-split xhi/xlo, fully cp.async ----
__global__ void __launch_bounds__(256, 1) gemm_mma_kernel(int which, int bm0,
                                                          float* __restrict__ C) {
    extern __shared__ __align__(16) __nv_bfloat16 sm[];
    int tid = threadIdx.x;
    int bm = bm0 + blockIdx.x, bn = blockIdx.y;
    int warp = tid >> 5, lane = tid & 31;
    int wm = warp >> 1, wn = warp & 1;
    int gg = lane >> 2, tt = lane & 3;

    const __nv_bfloat16* Ah = g_xhi + (size_t)(bm*128) * HD;
    const __nv_bfloat16* Al = g_xlo + (size_t)(bm*128) * HD;
    const __nv_bfloat16* Bh = g_WThi[which] + (size_t)(bn*128) * HD;
    const __nv_bfloat16* Bl = g_WTlo[which] + (size_t)(bn*128) * HD;
    uint32_t sbase = smem_u32(sm);

    float acc[2][8][4];
    #pragma unroll
    for (int mt = 0; mt < 2; mt++)
        #pragma unroll
        for (int nt = 0; nt < 8; nt++)
            #pragma unroll
            for (int q = 0; q < 4; q++) acc[mt][nt][q] = 0.f;

    auto issue = [&](int kc, int buf) {
        uint32_t bb = sbase + buf * (BUF_ELEMS*2);
        #pragma unroll
        for (int it = 0; it < 4; it++) {
            int u = it*256 + tid;
            int row = u >> 3, seg = u & 7;
            size_t go = (size_t)row*HD + kc*64 + seg*8;
            uint32_t so = (row*ASTR + seg*8) * 2;
            cp_async16(bb + OFF_AH*2 + so, Ah + go);
            cp_async16(bb + OFF_AL*2 + so, Al + go);
            cp_async16(bb + OFF_BH*2 + so, Bh + go);
            cp_async16(bb + OFF_BL*2 + so, Bl + go);
        }
        CP_COMMIT();
    };

    issue(0, 0);
    #pragma unroll
    for (int kc = 0; kc < 4; kc++) {
        if (kc < 3) { issue(kc+1, (kc+1)&1); CP_WAIT(1); }
        else        { CP_WAIT(0); }
        __syncthreads();
        gemm_compute_chunk(sm + (kc&1)*BUF_ELEMS, acc, wm, wn, gg, tt);
        __syncthreads();
    }
    gemm_epilogue(acc, C, bm, bn, wm, wn, gg, tt);
}

// ---- layer-2 GEMM: A gathered from g_y via oldidx/gatev, split on the fly --
__global__ void __launch_bounds__(256, 1) gemm2_gather_kernel(float* __restrict__ C) {
    extern __shared__ __align__(16) __nv_bfloat16 sm[];
    int tid = threadIdx.x;
    int bm = blockIdx.x, bn = blockIdx.y;
    int warp = tid >> 5, lane = tid & 31;
    int wm = warp >> 1, wn = warp & 1;
    int gg = lane >> 2, tt = lane & 3;

    const __nv_bfloat16* Bh = g_WThi[1] + (size_t)(bn*128) * HD;
    const __nv_bfloat16* Bl = g_WTlo[1] + (size_t)(bn*128) * HD;
    uint32_t sbase = smem_u32(sm);

    float acc[2][8][4];
    #pragma unroll
    for (int mt = 0; mt < 2; mt++)
        #pragma unroll
        for (int nt = 0; nt < 8; nt++)
            #pragma unroll
            for (int q = 0; q < 4; q++) acc[mt][nt][q] = 0.f;

    auto issueB = [&](int kc, int buf) {
        uint32_t bb = sbase + buf * (BUF_ELEMS*2);
        #pragma unroll
        for (int it = 0; it < 4; it++) {
            int u = it*256 + tid;
            int row = u >> 3, seg = u & 7;
            size_t go = (size_t)row*HD + kc*64 + seg*8;
            uint32_t so = (row*ASTR + seg*8) * 2;
            cp_async16(bb + OFF_BH*2 + so, Bh + go);
            cp_async16(bb + OFF_BL*2 + so, Bl + go);
        }
        CP_COMMIT();
    };
    auto stageA = [&](int kc, int buf) {
        __nv_bfloat16* dst = sm + buf * BUF_ELEMS;
        #pragma unroll
        for (int it = 0; it < 4; it++) {
            int u = it*256 + tid;
            int row = u >> 3, seg = u & 7;
            int nid = bm*128 + row;
            int old = g_oldidx[nid];
            float gv = g_gatev[nid];
            const float4* yp = (const float4*)(g_y + (size_t)old*HD + kc*64 + seg*8);
            float4 v0 = yp[0], v1 = yp[1];
            v0.x *= gv; v0.y *= gv; v0.z *= gv; v0.w *= gv;
            v1.x *= gv; v1.y *= gv; v1.z *= gv; v1.w *= gv;
            uint2 h0, l0, h1, l1;
            split4(v0, h0, l0);
            split4(v1, h1, l1);
            int so = row*ASTR + seg*8;
            *(uint2*)(dst + OFF_AH + so)     = h0;
            *(uint2*)(dst + OFF_AH + so + 4) = h1;
            *(uint2*)(dst + OFF_AL + so)     = l0;
            *(uint2*)(dst + OFF_AL + so + 4) = l1;
        }
    };

    issueB(0, 0);
    stageA(0, 0);
    #pragma unroll
    for (int kc = 0; kc < 4; kc++) {
        if (kc < 3) {
            issueB(kc+1, (kc+1)&1);
            stageA(kc+1, (kc+1)&1);
            CP_WAIT(1);
        } else {
            CP_WAIT(0);
        }
        __syncthreads();
        gemm_compute_chunk(sm + (kc&1)*BUF_ELEMS, acc, wm, wn, gg, tt);
        __syncthreads();
    }
    gemm_epilogue(acc, C, bm, bn, wm, wn, gg, tt);
}

// ---------------- GCN aggregate + relu (node range; fused dots) -----------
__global__ void __launch_bounds__(256) gcn_agg_kernel(const float* __restrict__ b,
                                                      const float* __restrict__ wg,
                                                      int which, int node0) {
    __shared__ float sred[8];
    __shared__ float sred2[8];
    int tid = threadIdx.x;
    int grp = tid >> 6, lane = tid & 63, wid = tid >> 5;
    int i = node0 + blockIdx.x * 4 + grp;
    int rs = g_rowstart[i], c = g_cnt[i];
    const float4* h4 = (const float4*)g_h;
    float4 acc = {0.f, 0.f, 0.f, 0.f};
    int j = 0;
    for (; j + 4 <= c; j += 4) {
        int   s0 = g_csr[rs+j],   s1 = g_csr[rs+j+1],  s2 = g_csr[rs+j+2],  s3 = g_csr[rs+j+3];
        float w0 = g_csrw[rs+j],  w1 = g_csrw[rs+j+1], w2 = g_csrw[rs+j+2], w3 = g_csrw[rs+j+3];
        float4 x0 = h4[(size_t)s0*64 + lane];
        float4 x1 = h4[(size_t)s1*64 + lane];
        float4 x2 = h4[(size_t)s2*64 + lane];
        float4 x3 = h4[(size_t)s3*64 + lane];
        acc.x = fmaf(x0.x, w0, acc.x); acc.y = fmaf(x0.y, w0, acc.y);
        acc.z = fmaf(x0.z, w0, acc.z); acc.w = fmaf(x0.w, w0, acc.w);
        acc.x = fmaf(x1.x, w1, acc.x); acc.y = fmaf(x1.y, w1, acc.y);
        acc.z = fmaf(x1.z, w1, acc.z); acc.w = fmaf(x1.w, w1, acc.w);
        acc.x = fmaf(x2.x, w2, acc.x); acc.y = fmaf(x2.y, w2, acc.y);
        acc.z = fmaf(x2.z, w2, acc.z); acc.w = fmaf(x2.w, w2, acc.w);
        acc.x = fmaf(x3.x, w3, acc.x); acc.y = fmaf(x3.y, w3, acc.y);
        acc.z = fmaf(x3.z, w3, acc.z); acc.w = fmaf(x3.w, w3, acc.w);
    }
    for (; j < c; j++) {
        int   s0 = g_csr[rs+j];
        float w0 = g_csrw[rs+j];
        float4 x0 = h4[(size_t)s0*64 + lane];
        acc.x = fmaf(x0.x, w0, acc.x); acc.y = fmaf(x0.y, w0, acc.y);
        acc.z = fmaf(x0.z, w0, acc.z); acc.w = fmaf(x0.w, w0, acc.w);
    }
    float sl = 1.0f / g_deg[i];
    float4 xi = h4[(size_t)i*64 + lane];
    float4 bb = ((const float4*)b)[lane];
    float4 v;
    v.x = fmaxf(fmaf(xi.x, sl, acc.x) + bb.x, 0.f);
    v.y = fmaxf(fmaf(xi.y, sl, acc.y) + bb.y, 0.f);
    v.z = fmaxf(fmaf(xi.z, sl, acc.z) + bb.z, 0.f);
    v.w = fmaxf(fmaf(xi.w, sl, acc.w) + bb.w, 0.f);
    ((float4*)g_y)[(size_t)i*64 + lane] = v;
    float4 pn = ((const float4*)(g_pn + which*HD))[lane];
    float4 wg4 = ((const float4*)wg)[lane];
    float s  = v.x*pn.x + v.y*pn.y + v.z*pn.z + v.w*pn.w;
    float s2 = v.x*wg4.x + v.y*wg4.y + v.z*wg4.z + v.w*wg4.w;
    #pragma unroll
    for (int o = 16; o > 0; o >>= 1) {
        s  += __shfl_down_sync(0xffffffffu, s,  o);
        s2 += __shfl_down_sync(0xffffffffu, s2, o);
    }
    if ((tid & 31) == 0) { sred[wid] = s; sred2[wid] = s2; }
    __syncthreads();
    if (tid < 4) {
        int i2 = node0 + blockIdx.x*4 + tid;
        g_score[i2] = sred[2*tid]  + sred[2*tid+1];
        g_ydw[i2]   = sred2[2*tid] + sred2[2*tid+1];
    }
}

// -------- layer-1 fused top-k + gates + softmax + attention pool ----------
__global__ void topk1_fused_kernel(const float* __restrict__ bg) {
    __shared__ float sv[512];
    __shared__ int   si[512];
    __shared__ int   sold[256];
    __shared__ float scoef[256];
    __shared__ float rbuf[512];
    const int n_per = NPG, k = KP1;
    int g = blockIdx.x, tid = threadIdx.x;
    sv[tid] = g_score[g*n_per + tid];
    si[tid] = tid;
    __syncthreads();
    for (int ksz = 2; ksz <= n_per; ksz <<= 1) {
        for (int j = ksz >> 1; j > 0; j >>= 1) {
            int ixj = tid ^ j;
            if (ixj > tid) {
                bool asc = ((tid & ksz) == 0);
                float v1 = sv[tid], v2 = sv[ixj];
                int   i1 = si[tid], i2 = si[ixj];
                bool b12 = (v1 > v2) || (v1 == v2 && i1 < i2);
                if (asc != b12) {
                    sv[tid] = v2; si[tid] = i2;
                    sv[ixj] = v1; si[ixj] = i1;
                }
            }
            __syncthreads();
        }
    }
    float tanhv = 0.f, gate = -1e30f;
    int old = 0;
    if (tid < k) {
        old = g*n_per + si[tid];
        tanhv = tanhf(sv[tid]);
        int nid = g*k + tid;
        g_nof[old]    = nid;
        g_oldidx[nid] = old;
        g_gatev[nid]  = tanhv;
        sold[tid] = old;
        gate = tanhv * g_ydw[old] + bg[0];
    }
    __syncthreads();
    rbuf[tid] = gate;
    __syncthreads();
    for (int s = 256; s > 0; s >>= 1) {
        if (tid < s) rbuf[tid] = fmaxf(rbuf[tid], rbuf[tid+s]);
        __syncthreads();
    }
    float mx = rbuf[0];
    __syncthreads();
    float e = (tid < k) ? expf(gate - mx) : 0.f;
    rbuf[tid] = e;
    __syncthreads();
    for (int s = 256; s > 0; s >>= 1) {
        if (tid < s) rbuf[tid] += rbuf[tid+s];
        __syncthreads();
    }
    float inv = 1.f / rbuf[0];
    if (tid < k) scoef[tid] = e * inv * tanhv;
    __syncthreads();
    int f = tid & 255;
    int i0 = (tid < 256) ? 0 : k/2;
    int i1 = (tid < 256) ? k/2 : k;
    float acc = 0.f;
    for (int i = i0; i < i1; i++)
        acc = fmaf(scoef[i], g_y[(size_t)sold[i]*HD + f], acc);
    rbuf[tid] = acc;
    __syncthreads();
    if (tid < 256) g_out[g*HD + f] = rbuf[tid] + rbuf[tid+256];
}

// -------- layer-2 fused top-k + attention pool + projection head ----------
__global__ void topk2_head_kernel(const float* __restrict__ bg,
                                  const float* __restrict__ Wp1,
                                  const float* __restrict__ bp1,
                                  const float* __restrict__ Wp2,
                                  const float* __restrict__ bp2,
                                  float* __restrict__ out) {
    __shared__ float sv[256];
    __shared__ int   si[256];
    __shared__ int   sold[128];
    __shared__ float scoef[128];
    __shared__ float rbuf[256];
    __shared__ float o[HD];
    __shared__ float hs[PD];
    __shared__ float lg[PD];
    const int n_per = KP1, k = KP2;
    int g = blockIdx.x, tid = threadIdx.x;
    sv[tid] = g_score[g*n_per + tid];
    si[tid] = tid;
    __syncthreads();
    for (int ksz = 2; ksz <= n_per; ksz <<= 1) {
        for (int j = ksz >> 1; j > 0; j >>= 1) {
            int ixj = tid ^ j;
            if (ixj > tid) {
                bool asc = ((tid & ksz) == 0);
                float v1 = sv[tid], v2 = sv[ixj];
                int   i1 = si[tid], i2 = si[ixj];
                bool b12 = (v1 > v2) || (v1 == v2 && i1 < i2);
                if (asc != b12) {
                    sv[tid] = v2; si[tid] = i2;
                    sv[ixj] = v1; si[ixj] = i1;
                }
            }
            __syncthreads();
        }
    }
    float tanhv = 0.f, gate = -1e30f;
    int old = 0;
    if (tid < k) {
        old = g*n_per + si[tid];
        tanhv = tanhf(sv[tid]);
        sold[tid] = old;
        gate = tanhv * g_ydw[old] + bg[0];
    }
    __syncthreads();
    rbuf[tid] = gate;
    __syncthreads();
    for (int s = 128; s > 0; s >>= 1) {
        if (tid < s) rbuf[tid] = fmaxf(rbuf[tid], rbuf[tid+s]);
        __syncthreads();
    }
    float mx = rbuf[0];
    __syncthreads();
    float e = (tid < k) ? expf(gate - mx) : 0.f;
    rbuf[tid] = e;
    __syncthreads();
    for (int s = 128; s > 0; s >>= 1) {
        if (tid < s) rbuf[tid] += rbuf[tid+s];
        __syncthreads();
    }
    float inv = 1.f / rbuf[0];
    if (tid < k) scoef[tid] = e * inv * tanhv;
    __syncthreads();
    float acc = 0.f;
    for (int i = 0; i < k; i++)
        acc = fmaf(scoef[i], g_y[(size_t)sold[i]*HD + tid], acc);
    o[tid] = g_out[g*HD + tid] + acc;
    __syncthreads();
    if (tid < PD) {
        float s = bp1[tid];
        for (int kk = 0; kk < HD; kk++) s = fmaf(o[kk], Wp1[kk*PD + tid], s);
        hs[tid] = fmaxf(s, 0.f);
    }
    __syncthreads();
    if (tid < PD) {
        float s = bp2[tid];
        for (int kk = 0; kk < PD; kk++) s = fmaf(hs[kk], Wp2[kk*PD + tid], s);
        lg[tid] = s;
        rbuf[tid] = s * s;
    }
    __syncthreads();
    for (int s = 64; s > 0; s >>= 1) {
        if (tid < s) rbuf[tid] += rbuf[tid+s];
        __syncthreads();
    }
    float nrm = fmaxf(sqrtf(rbuf[0]), 1e-12f);
    if (tid < PD) out[g*PD + tid] = lg[tid] / nrm;
    out[BG*PD + g*HD + tid] = o[tid];
}

// ---------------- driver: staged-offset overlap, 1 side stream -----------
extern "C" void kernel_launch(void* const* d_in, const int* in_sizes, int n_in,
                              void* d_out, int out_size) {
    const int*   tokens = (const int*)  d_in[0];
    const int*   src    = (const int*)  d_in[1];
    const int*   dst    = (const int*)  d_in[2];
    const float* eattr  = (const float*)d_in[3];
    const float* emb    = (const float*)d_in[4];
    const float* W0     = (const float*)d_in[5];
    const float* b0     = (const float*)d_in[6];
    const float* W1     = (const float*)d_in[7];
    const float* b1     = (const float*)d_in[8];
    const float* p0     = (const float*)d_in[9];
    const float* p1     = (const float*)d_in[10];
    const float* wg     = (const float*)d_in[11];
    const float* bg     = (const float*)d_in[12];
    const float* Wp1    = (const float*)d_in[13];
    const float* bp1    = (const float*)d_in[14];
    const float* Wp2    = (const float*)d_in[15];
    const float* bp2    = (const float*)d_in[16];
    float* out = (float*)d_out;

    cudaFuncSetAttribute(gemm_mma_kernel,     cudaFuncAttributeMaxDynamicSharedMemorySize, GEMM_SMEM);
    cudaFuncSetAttribute(gemm2_gather_kernel, cudaFuncAttributeMaxDynamicSharedMemorySize, GEMM_SMEM);

    float* gh_dev = nullptr; cudaGetSymbolAddress((void**)&gh_dev, g_h);

    cudaStream_t s2;
    cudaStreamCreateWithFlags(&s2, cudaStreamNonBlocking);
    cudaEvent_t ev_fork, ev_w, ev_sa, ev_e1, ev_a1a, ev_t1, ev_e2;
    cudaEventCreateWithFlags(&ev_fork, cudaEventDisableTiming);
    cudaEventCreateWithFlags(&ev_w,    cudaEventDisableTiming);
    cudaEventCreateWithFlags(&ev_sa,   cudaEventDisableTiming);
    cudaEventCreateWithFlags(&ev_e1,   cudaEventDisableTiming);
    cudaEventCreateWithFlags(&ev_a1a,  cudaEventDisableTiming);
    cudaEventCreateWithFlags(&ev_t1,   cudaEventDisableTiming);
    cudaEventCreateWithFlags(&ev_e2,   cudaEventDisableTiming);

    cudaEventRecord(ev_fork, 0);
    cudaStreamWaitEvent(s2, ev_fork, 0);

    // s2: weights -> edge pipeline 1 -> gemm1a -> agg1a (half A, staged)
    wsplit_kernel<<<512, 256, 0, s2>>>(W0, W1);
    normp_kernel<<<2, HD, 0, s2>>>(p0, p1);
    cudaEventRecord(ev_w, s2);
    edge_build1_kernel<<<BG, 1024, 0, s2>>>(eattr, src, dst);
    cudaEventRecord(ev_e1, s2);

    // main: st halves
    st_encode_kernel<<<NN/8, 256>>>(tokens, emb, 0);
    cudaEventRecord(ev_sa, 0);
    st_encode_kernel<<<NN/8, 256>>>(tokens, emb, NN/2);

    // s2: gemm1a (rows 0..NN/2) then agg1a (graphs 0..31)
    cudaStreamWaitEvent(s2, ev_sa, 0);
    gemm_mma_kernel<<<dim3(NN/256, 2), 256, GEMM_SMEM, s2>>>(0, 0, gh_dev);
    gcn_agg_kernel<<<NN/8, 256, 0, s2>>>(b0, wg, 0, 0);
    cudaEventRecord(ev_a1a, s2);

    // main: gemm1b -> agg1b (overlaps agg1a on s2)
    cudaStreamWaitEvent(0, ev_w, 0);
    gemm_mma_kernel<<<dim3(NN/256, 2), 256, GEMM_SMEM>>>(0, NN/256, gh_dev);
    cudaStreamWaitEvent(0, ev_e1, 0);
    gcn_agg_kernel<<<NN/8, 256>>>(b0, wg, 0, NN/2);
    cudaStreamWaitEvent(0, ev_a1a, 0);
    topk1_fused_kernel<<<BG, 512>>>(bg);
    cudaEventRecord(ev_t1, 0);

    // s2: layer-2 edge pipeline overlaps gemm2 on main
    cudaStreamWaitEvent(s2, ev_t1, 0);
    edge_build2_kernel<<<BG, 1024, 0, s2>>>(src, dst);
    cudaEventRecord(ev_e2, s2);

    // main: gemm2 (fused pool-gather) -> agg2 -> topk2+head
    gemm2_gather_kernel<<<dim3(N2/128, 2), 256, GEMM_SMEM>>>(gh_dev);
    cudaStreamWaitEvent(0, ev_e2, 0);
    gcn_agg_kernel<<<N2/4, 256>>>(b1, wg, 1, 0);
    topk2_head_kernel<<<BG, 256>>>(bg, Wp1, bp1, Wp2, bp2, out);
}

// round 16
// speedup vs baseline: 1.0886x; 1.0301x over previous
#include <cuda_runtime.h>
#include <cuda_bf16.h>
#include <cstdint>

// ---------------- static problem config ----------------
#define BG   64
#define NPG  512
#define NN   (BG*NPG)     // 32768
#define EPG  8192
#define EE   (BG*EPG)     // 524288
#define LTOK 16
#define HD   256
#define PD   128
#define KP1  256
#define KP2  128
#define N2   (BG*KP1)     // 16384
#define HB   (BG/2)       // 32 graphs per half

// ---------------- device scratch ----------------
__device__ float g_w[EE];
__device__ float g_h[NN*HD];
__device__ float g_y[NN*HD];
__device__ __nv_bfloat16 g_xhi[NN*HD];
__device__ __nv_bfloat16 g_xlo[NN*HD];
__device__ float g_deg[NN];
__device__ float g_score[NN];
__device__ float g_ydw[NN];
__device__ float g_gatev[NN];
__device__ int   g_cnt[NN];
__device__ int   g_rowstart[NN];
__device__ int   g_csr[EE];
__device__ float g_csrw[EE];
__device__ int   g_nof[NN];
__device__ int   g_oldidx[NN];
__device__ float g_out[BG*HD];
__device__ float g_pn[2*HD];
__device__ __nv_bfloat16 g_WThi[2][HD*HD];
__device__ __nv_bfloat16 g_WTlo[2][HD*HD];

// ---------------- helpers ----------------
__device__ __forceinline__ uint32_t smem_u32(const void* p) {
    uint32_t a;
    asm("{ .reg .u64 t; cvta.to.shared.u64 t, %1; cvt.u32.u64 %0, t; }" : "=r"(a) : "l"(p));
    return a;
}
__device__ __forceinline__ void cp_async16(uint32_t dst, const void* src) {
    asm volatile("cp.async.ca.shared.global [%0], [%1], 16;" :: "r"(dst), "l"(src) : "memory");
}
#define CP_COMMIT() asm volatile("cp.async.commit_group;" ::: "memory")
#define CP_WAIT(n)  asm volatile("cp.async.wait_group %0;" :: "n"(n) : "memory")

__device__ __forceinline__ void split4(float4 v, uint2& hi, uint2& lo) {
    __nv_bfloat162 h0 = __floats2bfloat162_rn(v.x, v.y);
    __nv_bfloat162 h1 = __floats2bfloat162_rn(v.z, v.w);
    float rx = v.x - __bfloat162float(__low2bfloat16(h0));
    float ry = v.y - __bfloat162float(__high2bfloat16(h0));
    float rz = v.z - __bfloat162float(__low2bfloat16(h1));
    float rw = v.w - __bfloat162float(__high2bfloat16(h1));
    __nv_bfloat162 l0 = __floats2bfloat162_rn(rx, ry);
    __nv_bfloat162 l1 = __floats2bfloat162_rn(rz, rw);
    hi = make_uint2(*(uint32_t*)&h0, *(uint32_t*)&h1);
    lo = make_uint2(*(uint32_t*)&l0, *(uint32_t*)&l1);
}

// ---------------- ST encoder ----------------
__global__ void __launch_bounds__(256, 6) st_encode_kernel(const int* __restrict__ tokens,
                                                           const float* __restrict__ emb,
                                                           int node0) {
    int tid = threadIdx.x;
    int grp = tid >> 6, lane = tid & 63;
    int nbase = node0 + blockIdx.x * 4;
    int node = nbase + grp;
    __shared__ int toks[4*LTOK];
    if (tid < 4*LTOK) toks[tid] = tokens[nbase*LTOK + tid];
    if (lane == 0) g_nof[node] = -1;
    __syncthreads();
    const float4* emb4 = (const float4*)emb;
    float4 a0 = {0.f, 0.f, 0.f, 0.f};
    float4 a1 = {0.f, 0.f, 0.f, 0.f};
    int cnt = 0;
    #pragma unroll
    for (int l = 0; l < LTOK; l += 2) {
        int t0 = toks[grp*LTOK + l];
        int t1 = toks[grp*LTOK + l + 1];
        if (t0 != 0) {
            float4 v = emb4[(size_t)t0*64 + lane];
            a0.x += v.x; a0.y += v.y; a0.z += v.z; a0.w += v.w;
            cnt++;
        }
        if (t1 != 0) {
            float4 v = emb4[(size_t)t1*64 + lane];
            a1.x += v.x; a1.y += v.y; a1.z += v.z; a1.w += v.w;
            cnt++;
        }
    }
    float inv = 1.f / (float)(cnt > 0 ? cnt : 1);
    float4 acc;
    acc.x = (a0.x + a1.x) * inv;
    acc.y = (a0.y + a1.y) * inv;
    acc.z = (a0.z + a1.z) * inv;
    acc.w = (a0.w + a1.w) * inv;
    size_t o = (size_t)node*64 + lane;
    uint2 hi, lo;
    split4(acc, hi, lo);
    ((uint2*)g_xhi)[o] = hi;
    ((uint2*)g_xlo)[o] = lo;
}

// ---------------- W^T bf16 split ----------------
__global__ void wsplit_kernel(const float* __restrict__ W0, const float* __restrict__ W1) {
    int b = blockIdx.x;
    int which = b >> 8, k = b & 255, n = threadIdx.x;
    const float* W = which ? W1 : W0;
    float v = W[k*HD + n];
    __nv_bfloat16 hi = __float2bfloat16(v);
    float lo = v - __bfloat162float(hi);
    g_WThi[which][n*HD + k] = hi;
    g_WTlo[which][n*HD + k] = __float2bfloat16(lo);
}

// ---------------- normalized p0,p1 ----------------
__global__ void normp_kernel(const float* __restrict__ p0, const float* __restrict__ p1) {
    __shared__ float red[HD];
    int which = blockIdx.x, tid = threadIdx.x;
    const float* p = which ? p1 : p0;
    float v = p[tid];
    red[tid] = v*v; __syncthreads();
    for (int s = HD/2; s > 0; s >>= 1) {
        if (tid < s) red[tid] += red[tid+s];
        __syncthreads();
    }
    g_pn[which*HD + tid] = v / sqrtf(red[0]);
}

// ======== fused edge pipeline, layer 1 =========
__global__ void __launch_bounds__(1024) edge_build1_kernel(const float* __restrict__ ea,
                                                           const int* __restrict__ src,
                                                           const int* __restrict__ dst) {
    __shared__ float sdeg[NPG];
    __shared__ int   scnt[NPG];
    __shared__ float sdinv[NPG];
    __shared__ int   scur[NPG];
    __shared__ int   sscan[NPG];
    int g = blockIdx.x, tid = threadIdx.x;
    int ebase = g * EPG;
    if (tid < NPG) { sdeg[tid] = 1.0f; scnt[tid] = 0; }
    __syncthreads();
    #pragma unroll
    for (int k = 0; k < EPG/1024; k++) {
        int e = ebase + k*1024 + tid;
        float w = 0.5f * (ea[2*e] + ea[2*e+1]);
        g_w[e] = w;
        int dl = dst[e] - g*NPG;
        atomicAdd(&sdeg[dl], w);
        atomicAdd(&scnt[dl], 1);
    }
    __syncthreads();
    int c = 0;
    if (tid < NPG) {
        int node = g*NPG + tid;
        float dg = sdeg[tid];
        c = scnt[tid];
        sdinv[tid] = rsqrtf(dg);
        g_deg[node] = dg;
        g_cnt[node] = c;
        sscan[tid] = c;
    }
    __syncthreads();
    for (int off = 1; off < NPG; off <<= 1) {
        int v = (tid >= off && tid < NPG) ? sscan[tid-off] : 0;
        __syncthreads();
        if (tid < NPG) sscan[tid] += v;
        __syncthreads();
    }
    if (tid < NPG) {
        int rs = ebase + sscan[tid] - c;
        g_rowstart[g*NPG + tid] = rs;
        scur[tid] = rs;
    }
    __syncthreads();
    #pragma unroll
    for (int k = 0; k < EPG/1024; k++) {
        int e = ebase + k*1024 + tid;
        int sl = src[e] - g*NPG;
        int dl = dst[e] - g*NPG;
        float w = g_w[e];
        int pos = atomicAdd(&scur[dl], 1);
        g_csr[pos]  = g*NPG + sl;
        g_csrw[pos] = sdinv[sl] * w * sdinv[dl];
    }
}

// ======== fused edge pipeline, layer 2 (graph range) ======
__global__ void __launch_bounds__(1024) edge_build2_kernel(const int* __restrict__ src,
                                                           const int* __restrict__ dst,
                                                           int g0) {
    __shared__ float sdeg[KP1];
    __shared__ int   scnt[KP1];
    __shared__ float sdinv[KP1];
    __shared__ int   scur[KP1];
    __shared__ int   sscan[KP1];
    int g = g0 + blockIdx.x, tid = threadIdx.x;
    int ebase = g * EPG;
    if (tid < KP1) { sdeg[tid] = 1.0f; scnt[tid] = 0; }
    __syncthreads();
    #pragma unroll
    for (int k = 0; k < EPG/1024; k++) {
        int e = ebase + k*1024 + tid;
        int ns = g_nof[src[e]], nd = g_nof[dst[e]];
        if (ns >= 0 && nd >= 0) {
            float w = g_w[e];
            int dl = nd - g*KP1;
            atomicAdd(&sdeg[dl], w);
            atomicAdd(&scnt[dl], 1);
        }
    }
    __syncthreads();
    int c = 0;
    if (tid < KP1) {
        int node = g*KP1 + tid;
        float dg = sdeg[tid];
        c = scnt[tid];
        sdinv[tid] = rsqrtf(dg);
        g_deg[node] = dg;
        g_cnt[node] = c;
        sscan[tid] = c;
    }
    __syncthreads();
    for (int off = 1; off < KP1; off <<= 1) {
        int v = (tid >= off && tid < KP1) ? sscan[tid-off] : 0;
        __syncthreads();
        if (tid < KP1) sscan[tid] += v;
        __syncthreads();
    }
    if (tid < KP1) {
        int rs = ebase + sscan[tid] - c;
        g_rowstart[g*KP1 + tid] = rs;
        scur[tid] = rs;
    }
    __syncthreads();
    #pragma unroll
    for (int k = 0; k < EPG/1024; k++) {
        int e = ebase + k*1024 + tid;
        int ns = g_nof[src[e]], nd = g_nof[dst[e]];
        if (ns >= 0 && nd >= 0) {
            float w = g_w[e];
            int sl = ns - g*KP1, dl = nd - g*KP1;
            int pos = atomicAdd(&scur[dl], 1);
            g_csr[pos]  = ns;
            g_csrw[pos] = sdinv[sl] * w * sdinv[dl];
        }
    }
}

// ================= GEMM common =================
#define ASTR 72
#define OFF_AH 0
#define OFF_AL (128*ASTR)
#define OFF_BH (2*128*ASTR)
#define OFF_BL (3*128*ASTR)
#define BUF_ELEMS (4*128*ASTR)
#define GEMM_SMEM (2*BUF_ELEMS*2)

__device__ __forceinline__ void mma_bf16(float* c, const uint32_t* a,
                                         uint32_t b0, uint32_t b1) {
    asm volatile(
        "mma.sync.aligned.m16n8k16.row.col.f32.bf16.bf16.f32 "
        "{%0,%1,%2,%3},{%4,%5,%6,%7},{%8,%9},{%0,%1,%2,%3};"
        : "+f"(c[0]), "+f"(c[1]), "+f"(c[2]), "+f"(c[3])
        : "r"(a[0]), "r"(a[1]), "r"(a[2]), "r"(a[3]), "r"(b0), "r"(b1));
}

__device__ __forceinline__ void gemm_compute_chunk(const __nv_bfloat16* buf,
                                                   float acc[2][8][4],
                                                   int wm, int wn, int gg, int tt) {
    #pragma unroll
    for (int ks = 0; ks < 4; ks++) {
        uint32_t ah[2][4], al[2][4];
        #pragma unroll
        for (int mt = 0; mt < 2; mt++) {
            int r0 = wm*32 + mt*16 + gg;
            const __nv_bfloat16* bh = buf + ks*16 + tt*2;
            ah[mt][0] = *(const uint32_t*)(bh + OFF_AH + r0*ASTR);
            ah[mt][1] = *(const uint32_t*)(bh + OFF_AH + (r0+8)*ASTR);
            ah[mt][2] = *(const uint32_t*)(bh + OFF_AH + r0*ASTR + 8);
            ah[mt][3] = *(const uint32_t*)(bh + OFF_AH + (r0+8)*ASTR + 8);
            al[mt][0] = *(const uint32_t*)(bh + OFF_AL + r0*ASTR);
            al[mt][1] = *(const uint32_t*)(bh + OFF_AL + (r0+8)*ASTR);
            al[mt][2] = *(const uint32_t*)(bh + OFF_AL + r0*ASTR + 8);
            al[mt][3] = *(const uint32_t*)(bh + OFF_AL + (r0+8)*ASTR + 8);
        }
        #pragma unroll
        for (int nt = 0; nt < 8; nt++) {
            int n0 = wn*64 + nt*8 + gg;
            const __nv_bfloat16* bb2 = buf + n0*ASTR + ks*16 + tt*2;
            uint32_t bh0 = *(const uint32_t*)(bb2 + OFF_BH);
            uint32_t bh1 = *(const uint32_t*)(bb2 + OFF_BH + 8);
            uint32_t bl0 = *(const uint32_t*)(bb2 + OFF_BL);
            uint32_t bl1 = *(const uint32_t*)(bb2 + OFF_BL + 8);
            #pragma unroll
            for (int mt = 0; mt < 2; mt++) {
                mma_bf16(acc[mt][nt], ah[mt], bh0, bh1);
                mma_bf16(acc[mt][nt], al[mt], bh0, bh1);
                mma_bf16(acc[mt][nt], ah[mt], bl0, bl1);
            }
        }
    }
}

__device__ __forceinline__ void gemm_epilogue(float acc[2][8][4], float* C,
                                              int bm, int bn, int wm, int wn,
                                              int gg, int tt) {
    #pragma unroll
    for (int mt = 0; mt < 2; mt++) {
        int row = bm*128 + wm*32 + mt*16 + gg;
        #pragma unroll
        for (int nt = 0; nt < 8; nt++) {
            int col = bn*128 + wn*64 + nt*8 + tt*2;
            float2 v0 = {acc[mt][nt][0], acc[mt][nt][1]};
            float2 v1 = {acc[mt][nt][2], acc[mt][nt][3]};
            *(float2*)(C + (size_t)row*HD + col)     = v0;
            *(float2*)(C + (size_t)(row+8)*HD + col) = v1;
        }
    }
}

// ---- layer-1 GEMM ----
__global__ void __launch_bounds__(256, 1) gemm_mma_kernel(int which, int bm0,
                                                          float* __restrict__ C) {
    extern __shared__ __align__(16) __nv_bfloat16 sm[];
    int tid = threadIdx.x;
    int bm = bm0 + blockIdx.x, bn = blockIdx.y;
    int warp = tid >> 5, lane = tid & 31;
    int wm = warp >> 1, wn = warp & 1;
    int gg = lane >> 2, tt = lane & 3;

    const __nv_bfloat16* Ah = g_xhi + (size_t)(bm*128) * HD;
    const __nv_bfloat16* Al = g_xlo + (size_t)(bm*128) * HD;
    const __nv_bfloat16* Bh = g_WThi[which] + (size_t)(bn*128) * HD;
    const __nv_bfloat16* Bl = g_WTlo[which] + (size_t)(bn*128) * HD;
    uint32_t sbase = smem_u32(sm);

    float acc[2][8][4];
    #pragma unroll
    for (int mt = 0; mt < 2; mt++)
        #pragma unroll
        for (int nt = 0; nt < 8; nt++)
            #pragma unroll
            for (int q = 0; q < 4; q++) acc[mt][nt][q] = 0.f;

    auto issue = [&](int kc, int buf) {
        uint32_t bb = sbase + buf * (BUF_ELEMS*2);
        #pragma unroll
        for (int it = 0; it < 4; it++) {
            int u = it*256 + tid;
            int row = u >> 3, seg = u & 7;
            size_t go = (size_t)row*HD + kc*64 + seg*8;
            uint32_t so = (row*ASTR + seg*8) * 2;
            cp_async16(bb + OFF_AH*2 + so, Ah + go);
            cp_async16(bb + OFF_AL*2 + so, Al + go);
            cp_async16(bb + OFF_BH*2 + so, Bh + go);
            cp_async16(bb + OFF_BL*2 + so, Bl + go);
        }
        CP_COMMIT();
    };

    issue(0, 0);
    #pragma unroll
    for (int kc = 0; kc < 4; kc++) {
        if (kc < 3) { issue(kc+1, (kc+1)&1); CP_WAIT(1); }
        else        { CP_WAIT(0); }
        __syncthreads();
        gemm_compute_chunk(sm + (kc&1)*BUF_ELEMS, acc, wm, wn, gg, tt);
        __syncthreads();
    }
    gemm_epilogue(acc, C, bm, bn, wm, wn, gg, tt);
}

// ---- layer-2 GEMM with fused pool-gather (tile range) ----
__global__ void __launch_bounds__(256, 1) gemm2_gather_kernel(int bm0, float* __restrict__ C) {
    extern __shared__ __align__(16) __nv_bfloat16 sm[];
    int tid = threadIdx.x;
    int bm = bm0 + blockIdx.x, bn = blockIdx.y;
    int warp = tid >> 5, lane = tid & 31;
    int wm = warp >> 1, wn = warp & 1;
    int gg = lane >> 2, tt = lane & 3;

    const __nv_bfloat16* Bh = g_WThi[1] + (size_t)(bn*128) * HD;
    const __nv_bfloat16* Bl = g_WTlo[1] + (size_t)(bn*128) * HD;
    uint32_t sbase = smem_u32(sm);

    float acc[2][8][4];
    #pragma unroll
    for (int mt = 0; mt < 2; mt++)
        #pragma unroll
        for (int nt = 0; nt < 8; nt++)
            #pragma unroll
            for (int q = 0; q < 4; q++) acc[mt][nt][q] = 0.f;

    auto issueB = [&](int kc, int buf) {
        uint32_t bb = sbase + buf * (BUF_ELEMS*2);
        #pragma unroll
        for (int it = 0; it < 4; it++) {
            int u = it*256 + tid;
            int row = u >> 3, seg = u & 7;
            size_t go = (size_t)row*HD + kc*64 + seg*8;
            uint32_t so = (row*ASTR + seg*8) * 2;
            cp_async16(bb + OFF_BH*2 + so, Bh + go);
            cp_async16(bb + OFF_BL*2 + so, Bl + go);
        }
        CP_COMMIT();
    };
    auto stageA = [&](int kc, int buf) {
        __nv_bfloat16* dst = sm + buf * BUF_ELEMS;
        #pragma unroll
        for (int it = 0; it < 4; it++) {
            int u = it*256 + tid;
            int row = u >> 3, seg = u & 7;
            int nid = bm*128 + row;
            int old = g_oldidx[nid];
            float gv = g_gatev[nid];
            const float4* yp = (const float4*)(g_y + (size_t)old*HD + kc*64 + seg*8);
            float4 v0 = yp[0], v1 = yp[1];
            v0.x *= gv; v0.y *= gv; v0.z *= gv; v0.w *= gv;
            v1.x *= gv; v1.y *= gv; v1.z *= gv; v1.w *= gv;
            uint2 h0, l0, h1, l1;
            split4(v0, h0, l0);
            split4(v1, h1, l1);
            int so = row*ASTR + seg*8;
            *(uint2*)(dst + OFF_AH + so)     = h0;
            *(uint2*)(dst + OFF_AH + so + 4) = h1;
            *(uint2*)(dst + OFF_AL + so)     = l0;
            *(uint2*)(dst + OFF_AL + so + 4) = l1;
        }
    };

    issueB(0, 0);
    stageA(0, 0);
    #pragma unroll
    for (int kc = 0; kc < 4; kc++) {
        if (kc < 3) {
            issueB(kc+1, (kc+1)&1);
            stageA(kc+1, (kc+1)&1);
            CP_WAIT(1);
        } else {
            CP_WAIT(0);
        }
        __syncthreads();
        gemm_compute_chunk(sm + (kc&1)*BUF_ELEMS, acc, wm, wn, gg, tt);
        __syncthreads();
    }
    gemm_epilogue(acc, C, bm, bn, wm, wn, gg, tt);
}

// ---------------- GCN aggregate + relu (node range; fused dots) -----------
__global__ void __launch_bounds__(256) gcn_agg_kernel(const float* __restrict__ b,
                                                      const float* __restrict__ wg,
                                                      int which, int node0) {
    __shared__ float sred[8];
    __shared__ float sred2[8];
    int tid = threadIdx.x;
    int grp = tid >> 6, lane = tid & 63, wid = tid >> 5;
    int i = node0 + blockIdx.x * 4 + grp;
    int rs = g_rowstart[i], c = g_cnt[i];
    const float4* h4 = (const float4*)g_h;
    float4 acc = {0.f, 0.f, 0.f, 0.f};
    int j = 0;
    for (; j + 4 <= c; j += 4) {
        int   s0 = g_csr[rs+j],   s1 = g_csr[rs+j+1],  s2 = g_csr[rs+j+2],  s3 = g_csr[rs+j+3];
        float w0 = g_csrw[rs+j],  w1 = g_csrw[rs+j+1], w2 = g_csrw[rs+j+2], w3 = g_csrw[rs+j+3];
        float4 x0 = h4[(size_t)s0*64 + lane];
        float4 x1 = h4[(size_t)s1*64 + lane];
        float4 x2 = h4[(size_t)s2*64 + lane];
        float4 x3 = h4[(size_t)s3*64 + lane];
        acc.x = fmaf(x0.x, w0, acc.x); acc.y = fmaf(x0.y, w0, acc.y);
        acc.z = fmaf(x0.z, w0, acc.z); acc.w = fmaf(x0.w, w0, acc.w);
        acc.x = fmaf(x1.x, w1, acc.x); acc.y = fmaf(x1.y, w1, acc.y);
        acc.z = fmaf(x1.z, w1, acc.z); acc.w = fmaf(x1.w, w1, acc.w);
        acc.x = fmaf(x2.x, w2, acc.x); acc.y = fmaf(x2.y, w2, acc.y);
        acc.z = fmaf(x2.z, w2, acc.z); acc.w = fmaf(x2.w, w2, acc.w);
        acc.x = fmaf(x3.x, w3, acc.x); acc.y = fmaf(x3.y, w3, acc.y);
        acc.z = fmaf(x3.z, w3, acc.z); acc.w = fmaf(x3.w, w3, acc.w);
    }
    for (; j < c; j++) {
        int   s0 = g_csr[rs+j];
        float w0 = g_csrw[rs+j];
        float4 x0 = h4[(size_t)s0*64 + lane];
        acc.x = fmaf(x0.x, w0, acc.x); acc.y = fmaf(x0.y, w0, acc.y);
        acc.z = fmaf(x0.z, w0, acc.z); acc.w = fmaf(x0.w, w0, acc.w);
    }
    float sl = 1.0f / g_deg[i];
    float4 xi = h4[(size_t)i*64 + lane];
    float4 bb = ((const float4*)b)[lane];
    float4 v;
    v.x = fmaxf(fmaf(xi.x, sl, acc.x) + bb.x, 0.f);
    v.y = fmaxf(fmaf(xi.y, sl, acc.y) + bb.y, 0.f);
    v.z = fmaxf(fmaf(xi.z, sl, acc.z) + bb.z, 0.f);
    v.w = fmaxf(fmaf(xi.w, sl, acc.w) + bb.w, 0.f);
    ((float4*)g_y)[(size_t)i*64 + lane] = v;
    float4 pn = ((const float4*)(g_pn + which*HD))[lane];
    float4 wg4 = ((const float4*)wg)[lane];
    float s  = v.x*pn.x + v.y*pn.y + v.z*pn.z + v.w*pn.w;
    float s2 = v.x*wg4.x + v.y*wg4.y + v.z*wg4.z + v.w*wg4.w;
    #pragma unroll
    for (int o = 16; o > 0; o >>= 1) {
        s  += __shfl_down_sync(0xffffffffu, s,  o);
        s2 += __shfl_down_sync(0xffffffffu, s2, o);
    }
    if ((tid & 31) == 0) { sred[wid] = s; sred2[wid] = s2; }
    __syncthreads();
    if (tid < 4) {
        int i2 = node0 + blockIdx.x*4 + tid;
        g_score[i2] = sred[2*tid]  + sred[2*tid+1];
        g_ydw[i2]   = sred2[2*tid] + sred2[2*tid+1];
    }
}

// -------- layer-1 fused top-k + gates + softmax + attention pool (g range) -
__global__ void topk1_fused_kernel(const float* __restrict__ bg, int g0) {
    __shared__ float sv[512];
    __shared__ int   si[512];
    __shared__ int   sold[256];
    __shared__ float scoef[256];
    __shared__ float rbuf[512];
    const int n_per = NPG, k = KP1;
    int g = g0 + blockIdx.x, tid = threadIdx.x;
    sv[tid] = g_score[g*n_per + tid];
    si[tid] = tid;
    __syncthreads();
    for (int ksz = 2; ksz <= n_per; ksz <<= 1) {
        for (int j = ksz >> 1; j > 0; j >>= 1) {
            int ixj = tid ^ j;
            if (ixj > tid) {
                bool asc = ((tid & ksz) == 0);
                float v1 = sv[tid], v2 = sv[ixj];
                int   i1 = si[tid], i2 = si[ixj];
                bool b12 = (v1 > v2) || (v1 == v2 && i1 < i2);
                if (asc != b12) {
                    sv[tid] = v2; si[tid] = i2;
                    sv[ixj] = v1; si[ixj] = i1;
                }
            }
            __syncthreads();
        }
    }
    float tanhv = 0.f, gate = -1e30f;
    int old = 0;
    if (tid < k) {
        old = g*n_per + si[tid];
        tanhv = tanhf(sv[tid]);
        int nid = g*k + tid;
        g_nof[old]    = nid;
        g_oldidx[nid] = old;
        g_gatev[nid]  = tanhv;
        sold[tid] = old;
        gate = tanhv * g_ydw[old] + bg[0];
    }
    __syncthreads();
    rbuf[tid] = gate;
    __syncthreads();
    for (int s = 256; s > 0; s >>= 1) {
        if (tid < s) rbuf[tid] = fmaxf(rbuf[tid], rbuf[tid+s]);
        __syncthreads();
    }
    float mx = rbuf[0];
    __syncthreads();
    float e = (tid < k) ? expf(gate - mx) : 0.f;
    rbuf[tid] = e;
    __syncthreads();
    for (int s = 256; s > 0; s >>= 1) {
        if (tid < s) rbuf[tid] += rbuf[tid+s];
        __syncthreads();
    }
    float inv = 1.f / rbuf[0];
    if (tid < k) scoef[tid] = e * inv * tanhv;
    __syncthreads();
    int f = tid & 255;
    int i0 = (tid < 256) ? 0 : k/2;
    int i1 = (tid < 256) ? k/2 : k;
    float acc = 0.f;
    for (int i = i0; i < i1; i++)
        acc = fmaf(scoef[i], g_y[(size_t)sold[i]*HD + f], acc);
    rbuf[tid] = acc;
    __syncthreads();
    if (tid < 256) g_out[g*HD + f] = rbuf[tid] + rbuf[tid+256];
}

// -------- layer-2 fused top-k + attention pool + head (g range) -----------
__global__ void topk2_head_kernel(const float* __restrict__ bg,
                                  const float* __restrict__ Wp1,
                                  const float* __restrict__ bp1,
                                  const float* __restrict__ Wp2,
                                  const float* __restrict__ bp2,
                                  float* __restrict__ out, int g0) {
    __shared__ float sv[256];
    __shared__ int   si[256];
    __shared__ int   sold[128];
    __shared__ float scoef[128];
    __shared__ float rbuf[256];
    __shared__ float o[HD];
    __shared__ float hs[PD];
    __shared__ float lg[PD];
    const int n_per = KP1, k = KP2;
    int g = g0 + blockIdx.x, tid = threadIdx.x;
    sv[tid] = g_score[g*n_per + tid];
    si[tid] = tid;
    __syncthreads();
    for (int ksz = 2; ksz <= n_per; ksz <<= 1) {
        for (int j = ksz >> 1; j > 0; j >>= 1) {
            int ixj = tid ^ j;
            if (ixj > tid) {
                bool asc = ((tid & ksz) == 0);
                float v1 = sv[tid], v2 = sv[ixj];
                int   i1 = si[tid], i2 = si[ixj];
                bool b12 = (v1 > v2) || (v1 == v2 && i1 < i2);
                if (asc != b12) {
                    sv[tid] = v2; si[tid] = i2;
                    sv[ixj] = v1; si[ixj] = i1;
                }
            }
            __syncthreads();
        }
    }
    float tanhv = 0.f, gate = -1e30f;
    int old = 0;
    if (tid < k) {
        old = g*n_per + si[tid];
        tanhv = tanhf(sv[tid]);
        sold[tid] = old;
        gate = tanhv * g_ydw[old] + bg[0];
    }
    __syncthreads();
    rbuf[tid] = gate;
    __syncthreads();
    for (int s = 128; s > 0; s >>= 1) {
        if (tid < s) rbuf[tid] = fmaxf(rbuf[tid], rbuf[tid+s]);
        __syncthreads();
    }
    float mx = rbuf[0];
    __syncthreads();
    float e = (tid < k) ? expf(gate - mx) : 0.f;
    rbuf[tid] = e;
    __syncthreads();
    for (int s = 128; s > 0; s >>= 1) {
        if (tid < s) rbuf[tid] += rbuf[tid+s];
        __syncthreads();
    }
    float inv = 1.f / rbuf[0];
    if (tid < k) scoef[tid] = e * inv * tanhv;
    __syncthreads();
    float acc = 0.f;
    for (int i = 0; i < k; i++)
        acc = fmaf(scoef[i], g_y[(size_t)sold[i]*HD + tid], acc);
    o[tid] = g_out[g*HD + tid] + acc;
    __syncthreads();
    if (tid < PD) {
        float s = bp1[tid];
        for (int kk = 0; kk < HD; kk++) s = fmaf(o[kk], Wp1[kk*PD + tid], s);
        hs[tid] = fmaxf(s, 0.f);
    }
    __syncthreads();
    if (tid < PD) {
        float s = bp2[tid];
        for (int kk = 0; kk < PD; kk++) s = fmaf(hs[kk], Wp2[kk*PD + tid], s);
        lg[tid] = s;
        rbuf[tid] = s * s;
    }
    __syncthreads();
    for (int s = 64; s > 0; s >>= 1) {
        if (tid < s) rbuf[tid] += rbuf[tid+s];
        __syncthreads();
    }
    float nrm = fmaxf(sqrtf(rbuf[0]), 1e-12f);
    if (tid < PD) out[g*PD + tid] = lg[tid] / nrm;
    out[BG*PD + g*HD + tid] = o[tid];
}

// -------- driver: full half-pipeline stage stagger, 1 side stream ---------
extern "C" void kernel_launch(void* const* d_in, const int* in_sizes, int n_in,
                              void* d_out, int out_size) {
    const int*   tokens = (const int*)  d_in[0];
    const int*   src    = (const int*)  d_in[1];
    const int*   dst    = (const int*)  d_in[2];
    const float* eattr  = (const float*)d_in[3];
    const float* emb    = (const float*)d_in[4];
    const float* W0     = (const float*)d_in[5];
    const float* b0     = (const float*)d_in[6];
    const float* W1     = (const float*)d_in[7];
    const float* b1     = (const float*)d_in[8];
    const float* p0     = (const float*)d_in[9];
    const float* p1     = (const float*)d_in[10];
    const float* wg     = (const float*)d_in[11];
    const float* bg     = (const float*)d_in[12];
    const float* Wp1    = (const float*)d_in[13];
    const float* bp1    = (const float*)d_in[14];
    const float* Wp2    = (const float*)d_in[15];
    const float* bp2    = (const float*)d_in[16];
    float* out = (float*)d_out;

    cudaFuncSetAttribute(gemm_mma_kernel,     cudaFuncAttributeMaxDynamicSharedMemorySize, GEMM_SMEM);
    cudaFuncSetAttribute(gemm2_gather_kernel, cudaFuncAttributeMaxDynamicSharedMemorySize, GEMM_SMEM);

    float* gh_dev = nullptr; cudaGetSymbolAddress((void**)&gh_dev, g_h);

    cudaStream_t s2;
    cudaStreamCreateWithFlags(&s2, cudaStreamNonBlocking);
    cudaEvent_t ev_fork, ev_w, ev_sa, ev_e1, ev_a1a, ev_g2a, ev_s2end;
    cudaEventCreateWithFlags(&ev_fork,  cudaEventDisableTiming);
    cudaEventCreateWithFlags(&ev_w,     cudaEventDisableTiming);
    cudaEventCreateWithFlags(&ev_sa,    cudaEventDisableTiming);
    cudaEventCreateWithFlags(&ev_e1,    cudaEventDisableTiming);
    cudaEventCreateWithFlags(&ev_a1a,   cudaEventDisableTiming);
    cudaEventCreateWithFlags(&ev_g2a,   cudaEventDisableTiming);
    cudaEventCreateWithFlags(&ev_s2end, cudaEventDisableTiming);

    cudaEventRecord(ev_fork, 0);
    cudaStreamWaitEvent(s2, ev_fork, 0);

    // s2 prelude: weights + layer-1 edge pipeline (whole batch)
    wsplit_kernel<<<512, 256, 0, s2>>>(W0, W1);
    normp_kernel<<<2, HD, 0, s2>>>(p0, p1);
    cudaEventRecord(ev_w, s2);
    edge_build1_kernel<<<BG, 1024, 0, s2>>>(eattr, src, dst);
    cudaEventRecord(ev_e1, s2);

    // main: st halves
    st_encode_kernel<<<NN/8, 256>>>(tokens, emb, 0);
    cudaEventRecord(ev_sa, 0);
    st_encode_kernel<<<NN/8, 256>>>(tokens, emb, NN/2);

    // ===== s2: full half-A pipeline (graphs 0..31) =====
    cudaStreamWaitEvent(s2, ev_sa, 0);
    gemm_mma_kernel<<<dim3(NN/256, 2), 256, GEMM_SMEM, s2>>>(0, 0, gh_dev);
    gcn_agg_kernel<<<NN/8, 256, 0, s2>>>(b0, wg, 0, 0);
    cudaEventRecord(ev_a1a, s2);
    topk1_fused_kernel<<<HB, 512, 0, s2>>>(bg, 0);
    edge_build2_kernel<<<HB, 1024, 0, s2>>>(src, dst, 0);
    gemm2_gather_kernel<<<dim3(N2/256, 2), 256, GEMM_SMEM, s2>>>(0, gh_dev);
    cudaEventRecord(ev_g2a, s2);
    gcn_agg_kernel<<<N2/8, 256, 0, s2>>>(b1, wg, 1, 0);
    topk2_head_kernel<<<HB, 256, 0, s2>>>(bg, Wp1, bp1, Wp2, bp2, out, 0);
    cudaEventRecord(ev_s2end, s2);

    // ===== main: full half-B pipeline (graphs 32..63) =====
    cudaStreamWaitEvent(0, ev_w, 0);
    gemm_mma_kernel<<<dim3(NN/256, 2), 256, GEMM_SMEM>>>(0, NN/256, gh_dev);
    cudaStreamWaitEvent(0, ev_e1, 0);
    gcn_agg_kernel<<<NN/8, 256>>>(b0, wg, 0, NN/2);
    topk1_fused_kernel<<<HB, 512>>>(bg, HB);
    cudaStreamWaitEvent(0, ev_a1a, 0);     // half-B L2 writes alias half-A L1 h/cnt regions
    edge_build2_kernel<<<HB, 1024>>>(src, dst, HB);
    gemm2_gather_kernel<<<dim3(N2/256, 2), 256, GEMM_SMEM>>>(N2/256, gh_dev);
    cudaStreamWaitEvent(0, ev_g2a, 0);     // agg2b writes y aliasing gemm2a's gather source
    gcn_agg_kernel<<<N2/8, 256>>>(b1, wg, 1, N2/2);
    topk2_head_kernel<<<HB, 256>>>(bg, Wp1, bp1, Wp2, bp2, out, HB);

    // join s2 back into the capture-origin stream
    cudaStreamWaitEvent(0, ev_s2end, 0);
}